// round 4
// baseline (speedup 1.0000x reference)
#include <cuda_runtime.h>
#include <cuda_fp16.h>

#define NMAX 50000
#define EMAX 800000
#define ETOTMAX (NMAX + EMAX)

// ---------------- scratch (device globals; no allocation allowed) ----------
__device__ __half g_h1h[NMAX * 256];   // layer-1 features (fp16, for gather)
__device__ float g_hagg[NMAX * 256];   // layer-1 aggregated output (+bias1, pre-ELU)
__device__ float g_asrc1[NMAX * 8];
__device__ float g_adst1[NMAX * 8];
__device__ float g_h2[NMAX * 16];
__device__ float g_asrc2[NMAX];
__device__ float g_adst2[NMAX];
__device__ int   g_cnt[NMAX];
__device__ int   g_off[NMAX + 1];
__device__ int   g_cur[NMAX];
__device__ int   g_csr[ETOTMAX];
__device__ int   g_is64;

__device__ __forceinline__ float lrelu(float x) { return x > 0.f ? x : 0.2f * x; }
__device__ __forceinline__ float warp_sum(float v) {
    #pragma unroll
    for (int o = 16; o; o >>= 1) v += __shfl_xor_sync(0xffffffffu, v, o);
    return v;
}
__device__ __forceinline__ float warp_max(float v) {
    #pragma unroll
    for (int o = 16; o; o >>= 1) v = fmaxf(v, __shfl_xor_sync(0xffffffffu, v, o));
    return v;
}

// ---------------- f32x2 packed math helpers (sm_103a) ----------------------
__device__ __forceinline__ unsigned long long pack2(float x, float y) {
    unsigned long long r;
    asm("mov.b64 %0, {%1, %2};" : "=l"(r)
        : "r"(__float_as_uint(x)), "r"(__float_as_uint(y)));
    return r;
}
__device__ __forceinline__ float2 unpack2(unsigned long long v) {
    unsigned lo, hi;
    asm("mov.b64 {%0, %1}, %2;" : "=r"(lo), "=r"(hi) : "l"(v));
    return make_float2(__uint_as_float(lo), __uint_as_float(hi));
}
#define FMA2(d, a, b) \
    asm("fma.rn.f32x2 %0, %1, %2, %3;" : "=l"(d) : "l"(a), "l"(b), "l"(d))

// ---------------- init: zero counters + detect int64 vs int32 --------------
__global__ void k_init(const int* __restrict__ ei32, int twoE, int N) {
    int i = blockIdx.x * blockDim.x + threadIdx.x;
    if (i < N) g_cnt[i] = 0;
    if (blockIdx.x == 0) {
        __shared__ int s_any;
        if (threadIdx.x == 0) s_any = 0;
        __syncthreads();
        int n = twoE < 2048 ? twoE : 2048;
        int nz = 0;
        for (int j = 2 * (int)threadIdx.x + 1; j < n; j += 512)
            nz |= (ei32[j] != 0);
        if (nz) atomicOr(&s_any, 1);
        __syncthreads();
        if (threadIdx.x == 0) g_is64 = s_any ? 0 : 1;
    }
}

// ---------------- GEMM1 + fused att logits (f32x2 core) --------------------
// block: 128 rows x 128 cols (= 4 heads). 256 threads, 8x8 microtile.
// thread's cols: {tx*4..tx*4+3} and {64+tx*4..64+tx*4+3} (conflict-free LDS).
__global__ __launch_bounds__(256, 2) void k_gemm1(const float* __restrict__ A,
                                                  const float* __restrict__ B,
                                                  const float* __restrict__ att_s,
                                                  const float* __restrict__ att_d,
                                                  int M) {
    __shared__ float As[8][132];
    __shared__ float Bs[8][128];
    int tid = threadIdx.x;
    int tx = tid & 15, ty = tid >> 4;
    int row0 = blockIdx.y * 128, col0 = blockIdx.x * 128;

    unsigned long long acc2[4][8];   // [u2][v]: lanes = rows 2*u2 (lo), 2*u2+1 (hi)
    #pragma unroll
    for (int u = 0; u < 4; u++)
        #pragma unroll
        for (int v = 0; v < 8; v++) acc2[u][v] = 0ull;

    int ar = tid >> 1, acq = (tid & 1) * 4;
    int br = tid >> 5, bc = (tid & 31) * 4;

    for (int k0 = 0; k0 < 128; k0 += 8) {
        float4 av = make_float4(0.f, 0.f, 0.f, 0.f);
        if (row0 + ar < M) av = *(const float4*)&A[(size_t)(row0 + ar) * 128 + k0 + acq];
        float4 bv = *(const float4*)&B[(size_t)(k0 + br) * 256 + col0 + bc];
        __syncthreads();
        As[acq + 0][ar] = av.x; As[acq + 1][ar] = av.y;
        As[acq + 2][ar] = av.z; As[acq + 3][ar] = av.w;
        *(float4*)&Bs[br][bc] = bv;
        __syncthreads();
        #pragma unroll
        for (int k = 0; k < 8; k++) {
            ulonglong2 aA = *(const ulonglong2*)&As[k][ty * 8];       // (a0,a1),(a2,a3)
            ulonglong2 aB = *(const ulonglong2*)&As[k][ty * 8 + 4];   // (a4,a5),(a6,a7)
            float4 bf0 = *(const float4*)&Bs[k][tx * 4];
            float4 bf1 = *(const float4*)&Bs[k][64 + tx * 4];
            unsigned long long a2[4] = {aA.x, aA.y, aB.x, aB.y};
            unsigned long long b2[8];
            b2[0] = pack2(bf0.x, bf0.x); b2[1] = pack2(bf0.y, bf0.y);
            b2[2] = pack2(bf0.z, bf0.z); b2[3] = pack2(bf0.w, bf0.w);
            b2[4] = pack2(bf1.x, bf1.x); b2[5] = pack2(bf1.y, bf1.y);
            b2[6] = pack2(bf1.z, bf1.z); b2[7] = pack2(bf1.w, bf1.w);
            #pragma unroll
            for (int u2 = 0; u2 < 4; u2++)
                #pragma unroll
                for (int v = 0; v < 8; v++) FMA2(acc2[u2][v], a2[u2], b2[v]);
        }
        __syncthreads();
    }

    // epilogue: attention logits + fp16 store
    int txl = tx & 7;
    int hA = (col0 >> 5) + (tx >> 3);     // head of first 4 cols
    int hB = hA + 2;                      // head of second 4 cols
    float asrA[4], adrA[4], asrB[4], adrB[4];
    #pragma unroll
    for (int v = 0; v < 4; v++) {
        asrA[v] = att_s[hA * 32 + txl * 4 + v];
        adrA[v] = att_d[hA * 32 + txl * 4 + v];
        asrB[v] = att_s[hB * 32 + txl * 4 + v];
        adrB[v] = att_d[hB * 32 + txl * 4 + v];
    }

    #pragma unroll
    for (int u = 0; u < 8; u++) {
        int grow = row0 + ty * 8 + u;
        float avv[8];
        #pragma unroll
        for (int v = 0; v < 8; v++) {
            float2 p = unpack2(acc2[u >> 1][v]);
            avv[v] = (u & 1) ? p.y : p.x;
        }
        float psA = 0.f, pdA = 0.f, psB = 0.f, pdB = 0.f;
        #pragma unroll
        for (int v = 0; v < 4; v++) {
            psA = fmaf(avv[v], asrA[v], psA);
            pdA = fmaf(avv[v], adrA[v], pdA);
            psB = fmaf(avv[v + 4], asrB[v], psB);
            pdB = fmaf(avv[v + 4], adrB[v], pdB);
        }
        #pragma unroll
        for (int o = 1; o <= 4; o <<= 1) {
            psA += __shfl_xor_sync(0xffffffffu, psA, o);
            pdA += __shfl_xor_sync(0xffffffffu, pdA, o);
            psB += __shfl_xor_sync(0xffffffffu, psB, o);
            pdB += __shfl_xor_sync(0xffffffffu, pdB, o);
        }
        if (grow < M) {
            if (txl == 0) {
                g_asrc1[grow * 8 + hA] = psA;
                g_adst1[grow * 8 + hA] = pdA;
                g_asrc1[grow * 8 + hB] = psB;
                g_adst1[grow * 8 + hB] = pdB;
            }
            __half2 q0 = __floats2half2_rn(avv[0], avv[1]);
            __half2 q1 = __floats2half2_rn(avv[2], avv[3]);
            __half2 q2 = __floats2half2_rn(avv[4], avv[5]);
            __half2 q3 = __floats2half2_rn(avv[6], avv[7]);
            uint2 s0, s1;
            s0.x = *(unsigned*)&q0; s0.y = *(unsigned*)&q1;
            s1.x = *(unsigned*)&q2; s1.y = *(unsigned*)&q3;
            *(uint2*)&g_h1h[(size_t)grow * 256 + col0 + tx * 4] = s0;
            *(uint2*)&g_h1h[(size_t)grow * 256 + col0 + 64 + tx * 4] = s1;
        }
    }
}

// ---------------- CSR build -------------------------------------------------
__global__ void k_hist(const void* __restrict__ ei, int E, int N) {
    int i = blockIdx.x * blockDim.x + threadIdx.x;
    if (i >= E + N) return;
    int d;
    if (i < E) {
        d = g_is64 ? (int)((const long long*)ei)[E + i]
                   : ((const int*)ei)[E + i];
    } else {
        d = i - E;
    }
    atomicAdd(&g_cnt[d], 1);
}

__global__ __launch_bounds__(1024) void k_scan(int N) {
    __shared__ int sd[1024];
    int tid = threadIdx.x;
    int chunk = (N + 1023) >> 10;
    int b = tid * chunk;
    int e = b + chunk; if (e > N) e = N;
    if (b > N) b = N;
    int loc = 0;
    for (int i = b; i < e; i++) loc += g_cnt[i];
    sd[tid] = loc;
    __syncthreads();
    for (int s = 1; s < 1024; s <<= 1) {
        int v = (tid >= s) ? sd[tid - s] : 0;
        __syncthreads();
        sd[tid] += v;
        __syncthreads();
    }
    int run = (tid == 0) ? 0 : sd[tid - 1];
    for (int i = b; i < e; i++) {
        g_off[i] = run; g_cur[i] = run;
        run += g_cnt[i];
    }
    if (tid == 1023) g_off[N] = sd[1023];
}

__global__ void k_scatter(const void* __restrict__ ei, int E, int N) {
    int i = blockIdx.x * blockDim.x + threadIdx.x;
    if (i >= E + N) return;
    int s, d;
    if (i < E) {
        if (g_is64) {
            const long long* p = (const long long*)ei;
            s = (int)p[i]; d = (int)p[E + i];
        } else {
            const int* p = (const int*)ei;
            s = p[i]; d = p[E + i];
        }
    } else {
        s = d = i - E;
    }
    int pos = atomicAdd(&g_cur[d], 1);
    g_csr[pos] = s;
}

// ---------------- layer-1 softmax + aggregation (warp per dst) -------------
// lane owns 8 contiguous cols [lane*8, lane*8+8) -> one head (lane>>2), one LDG.128/edge.
__device__ __forceinline__ void fma8(float* acc, uint4 pk, float w) {
    __half2 h0 = *(__half2*)&pk.x, h1 = *(__half2*)&pk.y;
    __half2 h2 = *(__half2*)&pk.z, h3 = *(__half2*)&pk.w;
    float2 f0 = __half22float2(h0), f1 = __half22float2(h1);
    float2 f2 = __half22float2(h2), f3 = __half22float2(h3);
    acc[0] = fmaf(f0.x, w, acc[0]); acc[1] = fmaf(f0.y, w, acc[1]);
    acc[2] = fmaf(f1.x, w, acc[2]); acc[3] = fmaf(f1.y, w, acc[3]);
    acc[4] = fmaf(f2.x, w, acc[4]); acc[5] = fmaf(f2.y, w, acc[5]);
    acc[6] = fmaf(f3.x, w, acc[6]); acc[7] = fmaf(f3.y, w, acc[7]);
}

__global__ __launch_bounds__(256) void k_agg1(const float* __restrict__ bias1, int N) {
    int d = (blockIdx.x * blockDim.x + threadIdx.x) >> 5;
    int lane = threadIdx.x & 31;
    if (d >= N) return;
    int beg = g_off[d], end = g_off[d + 1];
    int h = lane & 7, eg = lane >> 3;
    float adv = g_adst1[d * 8 + h];

    float m = -1e30f;
    for (int e = beg + eg; e < end; e += 4)
        m = fmaxf(m, lrelu(g_asrc1[g_csr[e] * 8 + h] + adv));
    m = fmaxf(m, __shfl_xor_sync(0xffffffffu, m, 8));
    m = fmaxf(m, __shfl_xor_sync(0xffffffffu, m, 16));

    float sum = 0.f;
    for (int e = beg + eg; e < end; e += 4)
        sum += __expf(lrelu(g_asrc1[g_csr[e] * 8 + h] + adv) - m);
    sum += __shfl_xor_sync(0xffffffffu, sum, 8);
    sum += __shfl_xor_sync(0xffffffffu, sum, 16);
    float inv = 1.f / (sum + 1e-16f);

    float acc[8];
    #pragma unroll
    for (int j = 0; j < 8; j++) acc[j] = 0.f;

    const uint4* base = (const uint4*)g_h1h;    // row = 32 uint4
    int hsrc = lane >> 2;
    int e = beg;
    for (; e + 1 < end; e += 2) {
        int s0 = g_csr[e], s1 = g_csr[e + 1];
        uint4 p0 = base[(size_t)s0 * 32 + lane];
        uint4 p1 = base[(size_t)s1 * 32 + lane];
        float w0 = 0.f, w1 = 0.f;
        if (lane < 8) {
            w0 = __expf(lrelu(g_asrc1[s0 * 8 + lane] + adv) - m) * inv;
            w1 = __expf(lrelu(g_asrc1[s1 * 8 + lane] + adv) - m) * inv;
        }
        float wa = __shfl_sync(0xffffffffu, w0, hsrc);
        float wb = __shfl_sync(0xffffffffu, w1, hsrc);
        fma8(acc, p0, wa);
        fma8(acc, p1, wb);
    }
    if (e < end) {
        int s0 = g_csr[e];
        uint4 p0 = base[(size_t)s0 * 32 + lane];
        float w0 = 0.f;
        if (lane < 8)
            w0 = __expf(lrelu(g_asrc1[s0 * 8 + lane] + adv) - m) * inv;
        float wa = __shfl_sync(0xffffffffu, w0, hsrc);
        fma8(acc, p0, wa);
    }

    const float* bp = bias1 + lane * 8;
    float* op = g_hagg + (size_t)d * 256 + lane * 8;
    float4 o0 = make_float4(acc[0] + bp[0], acc[1] + bp[1], acc[2] + bp[2], acc[3] + bp[3]);
    float4 o1 = make_float4(acc[4] + bp[4], acc[5] + bp[5], acc[6] + bp[6], acc[7] + bp[7]);
    *(float4*)op = o0;
    *(float4*)(op + 4) = o1;
}

// ---------------- GEMM2 (elu on the fly) + layer-2 logits ------------------
__global__ __launch_bounds__(256) void k_gemm2(const float* __restrict__ W2,
                                               const float* __restrict__ as2,
                                               const float* __restrict__ ad2, int N) {
    __shared__ float sh[16][260];
    __shared__ float sw[256 * 16];
    int tid = threadIdx.x;
    int row = tid >> 4, col = tid & 15;
    int n0 = blockIdx.x * 16;

    #pragma unroll
    for (int i = 0; i < 16; i++) sw[tid + i * 256] = W2[tid + i * 256];
    for (int i = tid; i < 16 * 256; i += 256) {
        int r = i >> 8, c = i & 255;
        int n = n0 + r;
        float v = (n < N) ? g_hagg[(size_t)n * 256 + c] : 0.f;
        sh[r][c] = v > 0.f ? v : expm1f(v);
    }
    __syncthreads();

    float acc = 0.f;
    #pragma unroll 8
    for (int k = 0; k < 256; k++) acc = fmaf(sh[row][k], sw[k * 16 + col], acc);

    float ps = acc * as2[col];
    float pd = acc * ad2[col];
    #pragma unroll
    for (int o = 8; o; o >>= 1) {
        ps += __shfl_xor_sync(0xffffffffu, ps, o);
        pd += __shfl_xor_sync(0xffffffffu, pd, o);
    }
    int n = n0 + row;
    if (n < N) {
        g_h2[n * 16 + col] = acc;
        if (col == 0) { g_asrc2[n] = ps; g_adst2[n] = pd; }
    }
}

// ---------------- layer-2 softmax + aggregation (warp per dst) -------------
__global__ __launch_bounds__(256) void k_agg2(const float* __restrict__ bias2,
                                              float* __restrict__ out, int N) {
    int d = (blockIdx.x * blockDim.x + threadIdx.x) >> 5;
    int lane = threadIdx.x & 31;
    if (d >= N) return;
    int beg = g_off[d], end = g_off[d + 1];
    float ad = g_adst2[d];

    float m = -1e30f;
    for (int e = beg + lane; e < end; e += 32)
        m = fmaxf(m, lrelu(g_asrc2[g_csr[e]] + ad));
    m = warp_max(m);

    float sum = 0.f;
    for (int e = beg + lane; e < end; e += 32)
        sum += __expf(lrelu(g_asrc2[g_csr[e]] + ad) - m);
    sum = warp_sum(sum);
    float inv = 1.f / (sum + 1e-16f);

    // two edges per iteration: half-warps process e, e+1
    int half = lane >> 4, l16 = lane & 15;
    float acc = 0.f;
    for (int e0 = beg; e0 < end; e0 += 2) {
        int e = e0 + half;
        bool valid = e < end;
        int s = valid ? g_csr[e] : 0;
        float w = 0.f;
        if (l16 == 0 && valid)
            w = __expf(lrelu(g_asrc2[s] + ad) - m) * inv;
        w = __shfl_sync(0xffffffffu, w, lane & 16);
        float hv = valid ? g_h2[s * 16 + l16] : 0.f;
        acc = fmaf(hv, w, acc);
    }
    acc += __shfl_xor_sync(0xffffffffu, acc, 16);
    if (lane < 16) out[d * 16 + lane] = acc + bias2[lane];
}

// ---------------- launch ----------------------------------------------------
extern "C" void kernel_launch(void* const* d_in, const int* in_sizes, int n_in,
                              void* d_out, int out_size) {
    const float* x   = (const float*)d_in[0];
    const void*  ei  = d_in[1];
    const float* W1  = (const float*)d_in[2];
    const float* as1 = (const float*)d_in[3];
    const float* ad1 = (const float*)d_in[4];
    const float* b1  = (const float*)d_in[5];
    const float* W2  = (const float*)d_in[6];
    const float* as2 = (const float*)d_in[7];
    const float* ad2 = (const float*)d_in[8];
    const float* b2  = (const float*)d_in[9];
    float* out = (float*)d_out;

    int N = in_sizes[0] / 128;
    int E = in_sizes[1] / 2;
    int tot = E + N;

    k_init<<<(N + 511) / 512, 512>>>((const int*)ei, in_sizes[1], N);

    dim3 g1(2, (N + 127) / 128);
    k_gemm1<<<g1, 256>>>(x, W1, as1, ad1, N);

    k_hist<<<(tot + 255) / 256, 256>>>(ei, E, N);
    k_scan<<<1, 1024>>>(N);
    k_scatter<<<(tot + 255) / 256, 256>>>(ei, E, N);

    k_agg1<<<(N * 32 + 255) / 256, 256>>>(b1, N);
    k_gemm2<<<(N + 15) / 16, 256>>>(W2, as2, ad2, N);
    k_agg2<<<(N * 32 + 255) / 256, 256>>>(b2, out, N);
}

// round 5
// speedup vs baseline: 1.4902x; 1.4902x over previous
#include <cuda_runtime.h>
#include <cuda_fp16.h>

#define NMAX 50000
#define EMAX 800000
#define ETOTMAX (NMAX + EMAX)

// ---------------- scratch (device globals; no allocation allowed) ----------
__device__ __half g_h1h[NMAX * 256];   // layer-1 features (fp16, for gather)
__device__ float g_hagg[NMAX * 256];   // layer-1 aggregated output (+bias1, pre-ELU)
__device__ float g_asrc1[NMAX * 8];
__device__ float g_adst1[NMAX * 8];
__device__ float g_h2[NMAX * 16];
__device__ float g_asrc2[NMAX];
__device__ float g_adst2[NMAX];
__device__ int   g_cnt[NMAX];
__device__ int   g_off[NMAX + 1];
__device__ int   g_cur[NMAX];
__device__ int   g_csr[ETOTMAX];
__device__ int   g_bsum[256];
__device__ int   g_is64;

__device__ __forceinline__ float lrelu(float x) { return x > 0.f ? x : 0.2f * x; }
__device__ __forceinline__ float warp_sum(float v) {
    #pragma unroll
    for (int o = 16; o; o >>= 1) v += __shfl_xor_sync(0xffffffffu, v, o);
    return v;
}
__device__ __forceinline__ float warp_max(float v) {
    #pragma unroll
    for (int o = 16; o; o >>= 1) v = fmaxf(v, __shfl_xor_sync(0xffffffffu, v, o));
    return v;
}

// ---------------- init: zero counters + detect int64 vs int32 --------------
__global__ void k_init(const int* __restrict__ ei32, int twoE, int N) {
    int i = blockIdx.x * blockDim.x + threadIdx.x;
    if (i < N) g_cnt[i] = 0;
    if (blockIdx.x == 0) {
        __shared__ int s_any;
        if (threadIdx.x == 0) s_any = 0;
        __syncthreads();
        int n = twoE < 2048 ? twoE : 2048;
        int nz = 0;
        for (int j = 2 * (int)threadIdx.x + 1; j < n; j += 512)
            nz |= (ei32[j] != 0);
        if (nz) atomicOr(&s_any, 1);
        __syncthreads();
        if (threadIdx.x == 0) g_is64 = s_any ? 0 : 1;
    }
}

// ---------------- GEMM1 + fused att logits (R3 version) --------------------
__global__ __launch_bounds__(256, 2) void k_gemm1(const float* __restrict__ A,
                                                  const float* __restrict__ B,
                                                  const float* __restrict__ att_s,
                                                  const float* __restrict__ att_d,
                                                  int M) {
    __shared__ float As[8][132];
    __shared__ float Bs[8][128];
    int tid = threadIdx.x;
    int tx = tid & 15, ty = tid >> 4;
    int row0 = blockIdx.y * 128, col0 = blockIdx.x * 128;

    float acc[8][8];
    #pragma unroll
    for (int u = 0; u < 8; u++)
        #pragma unroll
        for (int v = 0; v < 8; v++) acc[u][v] = 0.f;

    int ar = tid >> 1, acq = (tid & 1) * 4;
    int br = tid >> 5, bc = (tid & 31) * 4;

    for (int k0 = 0; k0 < 128; k0 += 8) {
        float4 av = make_float4(0.f, 0.f, 0.f, 0.f);
        if (row0 + ar < M) av = *(const float4*)&A[(size_t)(row0 + ar) * 128 + k0 + acq];
        float4 bv = *(const float4*)&B[(size_t)(k0 + br) * 256 + col0 + bc];
        __syncthreads();
        As[acq + 0][ar] = av.x; As[acq + 1][ar] = av.y;
        As[acq + 2][ar] = av.z; As[acq + 3][ar] = av.w;
        *(float4*)&Bs[br][bc] = bv;
        __syncthreads();
        #pragma unroll
        for (int k = 0; k < 8; k++) {
            float a[8], b[8];
            *(float4*)&a[0] = *(float4*)&As[k][ty * 8];
            *(float4*)&a[4] = *(float4*)&As[k][ty * 8 + 4];
            *(float4*)&b[0] = *(float4*)&Bs[k][tx * 8];
            *(float4*)&b[4] = *(float4*)&Bs[k][tx * 8 + 4];
            #pragma unroll
            for (int u = 0; u < 8; u++)
                #pragma unroll
                for (int v = 0; v < 8; v++) acc[u][v] = fmaf(a[u], b[v], acc[u][v]);
        }
        __syncthreads();
    }

    int hb = (col0 >> 5) + (tx >> 2);
    float asr[8], adr[8];
    #pragma unroll
    for (int v = 0; v < 8; v++) {
        asr[v] = att_s[hb * 32 + (tx & 3) * 8 + v];
        adr[v] = att_d[hb * 32 + (tx & 3) * 8 + v];
    }

    #pragma unroll
    for (int u = 0; u < 8; u++) {
        int grow = row0 + ty * 8 + u;
        float ps = 0.f, pd = 0.f;
        #pragma unroll
        for (int v = 0; v < 8; v++) {
            ps = fmaf(acc[u][v], asr[v], ps);
            pd = fmaf(acc[u][v], adr[v], pd);
        }
        ps += __shfl_xor_sync(0xffffffffu, ps, 1);
        ps += __shfl_xor_sync(0xffffffffu, ps, 2);
        pd += __shfl_xor_sync(0xffffffffu, pd, 1);
        pd += __shfl_xor_sync(0xffffffffu, pd, 2);
        if (grow < M) {
            if ((tx & 3) == 0) {
                g_asrc1[grow * 8 + hb] = ps;
                g_adst1[grow * 8 + hb] = pd;
            }
            __half2 p0 = __floats2half2_rn(acc[u][0], acc[u][1]);
            __half2 p1 = __floats2half2_rn(acc[u][2], acc[u][3]);
            __half2 p2 = __floats2half2_rn(acc[u][4], acc[u][5]);
            __half2 p3 = __floats2half2_rn(acc[u][6], acc[u][7]);
            uint4 pk;
            pk.x = *(unsigned*)&p0; pk.y = *(unsigned*)&p1;
            pk.z = *(unsigned*)&p2; pk.w = *(unsigned*)&p3;
            *(uint4*)&g_h1h[(size_t)grow * 256 + col0 + tx * 8] = pk;
        }
    }
}

// ---------------- CSR build -------------------------------------------------
__global__ void k_hist(const void* __restrict__ ei, int E, int N) {
    int i = blockIdx.x * blockDim.x + threadIdx.x;
    if (i >= E + N) return;
    int d;
    if (i < E) {
        d = g_is64 ? (int)((const long long*)ei)[E + i]
                   : ((const int*)ei)[E + i];
    } else {
        d = i - E;
    }
    atomicAdd(&g_cnt[d], 1);
}

// ---- 3-phase parallel scan over g_cnt[0..N) -> g_off/g_cur -----------------
__global__ __launch_bounds__(256) void k_scan1(int N) {
    __shared__ int sd[256];
    int i = blockIdx.x * 256 + threadIdx.x;
    int v = (i < N) ? g_cnt[i] : 0;
    sd[threadIdx.x] = v;
    __syncthreads();
    #pragma unroll
    for (int s = 1; s < 256; s <<= 1) {
        int t = (threadIdx.x >= s) ? sd[threadIdx.x - s] : 0;
        __syncthreads();
        sd[threadIdx.x] += t;
        __syncthreads();
    }
    if (i < N) g_off[i] = sd[threadIdx.x] - v;   // local exclusive
    if (threadIdx.x == 255) g_bsum[blockIdx.x] = sd[255];
}

__global__ __launch_bounds__(256) void k_scan2(int nb) {
    __shared__ int sd[256];
    int v = (threadIdx.x < nb) ? g_bsum[threadIdx.x] : 0;
    sd[threadIdx.x] = v;
    __syncthreads();
    #pragma unroll
    for (int s = 1; s < 256; s <<= 1) {
        int t = (threadIdx.x >= s) ? sd[threadIdx.x - s] : 0;
        __syncthreads();
        sd[threadIdx.x] += t;
        __syncthreads();
    }
    if (threadIdx.x < nb) g_bsum[threadIdx.x] = sd[threadIdx.x] - v;  // exclusive
}

__global__ __launch_bounds__(256) void k_scan3(int N, int total) {
    int i = blockIdx.x * 256 + threadIdx.x;
    if (i < N) {
        int o = g_off[i] + g_bsum[blockIdx.x];
        g_off[i] = o;
        g_cur[i] = o;
    }
    if (i == 0) g_off[N] = total;
}

__global__ void k_scatter(const void* __restrict__ ei, int E, int N) {
    int i = blockIdx.x * blockDim.x + threadIdx.x;
    if (i >= E + N) return;
    int s, d;
    if (i < E) {
        if (g_is64) {
            const long long* p = (const long long*)ei;
            s = (int)p[i]; d = (int)p[E + i];
        } else {
            const int* p = (const int*)ei;
            s = p[i]; d = p[E + i];
        }
    } else {
        s = d = i - E;
    }
    int pos = atomicAdd(&g_cur[d], 1);
    g_csr[pos] = s;
}

// ---------------- layer-1 softmax + aggregation (R3 version) ---------------
__global__ __launch_bounds__(256) void k_agg1(const float* __restrict__ bias1, int N) {
    int d = (blockIdx.x * blockDim.x + threadIdx.x) >> 5;
    int lane = threadIdx.x & 31;
    if (d >= N) return;
    int beg = g_off[d], end = g_off[d + 1];
    int h = lane & 7, eg = lane >> 3;
    float adv = g_adst1[d * 8 + h];

    float m = -1e30f;
    for (int e = beg + eg; e < end; e += 4)
        m = fmaxf(m, lrelu(g_asrc1[g_csr[e] * 8 + h] + adv));
    m = fmaxf(m, __shfl_xor_sync(0xffffffffu, m, 8));
    m = fmaxf(m, __shfl_xor_sync(0xffffffffu, m, 16));

    float sum = 0.f;
    for (int e = beg + eg; e < end; e += 4)
        sum += __expf(lrelu(g_asrc1[g_csr[e] * 8 + h] + adv) - m);
    sum += __shfl_xor_sync(0xffffffffu, sum, 8);
    sum += __shfl_xor_sync(0xffffffffu, sum, 16);
    float inv = 1.f / (sum + 1e-16f);

    float2 acc[4];
    #pragma unroll
    for (int j = 0; j < 4; j++) acc[j] = make_float2(0.f, 0.f);
    int hj[4];
    #pragma unroll
    for (int j = 0; j < 4; j++) hj[j] = j * 2 + (lane >> 4);

    const __half2* base = (const __half2*)g_h1h;
    for (int e = beg; e < end; e++) {
        int s = g_csr[e];
        float w = 0.f;
        if (lane < 8)
            w = __expf(lrelu(g_asrc1[s * 8 + lane] + adv) - m) * inv;
        const __half2* hp = base + (size_t)s * 128 + lane;
        #pragma unroll
        for (int j = 0; j < 4; j++) {
            float wj = __shfl_sync(0xffffffffu, w, hj[j]);
            float2 f = __half22float2(hp[j * 32]);
            acc[j].x = fmaf(f.x, wj, acc[j].x);
            acc[j].y = fmaf(f.y, wj, acc[j].y);
        }
    }
    float* op = g_hagg + (size_t)d * 256;
    #pragma unroll
    for (int j = 0; j < 4; j++) {
        int c = j * 64 + lane * 2;
        float2 bv = *(const float2*)&bias1[c];
        float2 o = make_float2(acc[j].x + bv.x, acc[j].y + bv.y);
        *(float2*)&op[c] = o;
    }
}

// ---------------- GEMM2 (elu on the fly) + layer-2 logits ------------------
__global__ __launch_bounds__(256) void k_gemm2(const float* __restrict__ W2,
                                               const float* __restrict__ as2,
                                               const float* __restrict__ ad2, int N) {
    __shared__ float sh[16][260];
    __shared__ float sw[256 * 16];
    int tid = threadIdx.x;
    int row = tid >> 4, col = tid & 15;
    int n0 = blockIdx.x * 16;

    #pragma unroll
    for (int i = 0; i < 16; i++) sw[tid + i * 256] = W2[tid + i * 256];
    for (int i = tid; i < 16 * 256; i += 256) {
        int r = i >> 8, c = i & 255;
        int n = n0 + r;
        float v = (n < N) ? g_hagg[(size_t)n * 256 + c] : 0.f;
        sh[r][c] = v > 0.f ? v : expm1f(v);
    }
    __syncthreads();

    float acc = 0.f;
    #pragma unroll 8
    for (int k = 0; k < 256; k++) acc = fmaf(sh[row][k], sw[k * 16 + col], acc);

    float ps = acc * as2[col];
    float pd = acc * ad2[col];
    #pragma unroll
    for (int o = 8; o; o >>= 1) {
        ps += __shfl_xor_sync(0xffffffffu, ps, o);
        pd += __shfl_xor_sync(0xffffffffu, pd, o);
    }
    int n = n0 + row;
    if (n < N) {
        g_h2[n * 16 + col] = acc;
        if (col == 0) { g_asrc2[n] = ps; g_adst2[n] = pd; }
    }
}

// ---------------- layer-2 softmax + aggregation (R3 version) ---------------
__global__ __launch_bounds__(256) void k_agg2(const float* __restrict__ bias2,
                                              float* __restrict__ out, int N) {
    int d = (blockIdx.x * blockDim.x + threadIdx.x) >> 5;
    int lane = threadIdx.x & 31;
    if (d >= N) return;
    int beg = g_off[d], end = g_off[d + 1];
    float ad = g_adst2[d];

    float m = -1e30f;
    for (int e = beg + lane; e < end; e += 32)
        m = fmaxf(m, lrelu(g_asrc2[g_csr[e]] + ad));
    m = warp_max(m);

    float sum = 0.f;
    for (int e = beg + lane; e < end; e += 32)
        sum += __expf(lrelu(g_asrc2[g_csr[e]] + ad) - m);
    sum = warp_sum(sum);
    float inv = 1.f / (sum + 1e-16f);

    float acc = 0.f;
    for (int e = beg; e < end; e++) {
        int s = g_csr[e];
        float w = 0.f;
        if (lane == 0) w = __expf(lrelu(g_asrc2[s] + ad) - m) * inv;
        w = __shfl_sync(0xffffffffu, w, 0);
        if (lane < 16) acc = fmaf(g_h2[s * 16 + lane], w, acc);
    }
    if (lane < 16) out[d * 16 + lane] = acc + bias2[lane];
}

// ---------------- launch ----------------------------------------------------
extern "C" void kernel_launch(void* const* d_in, const int* in_sizes, int n_in,
                              void* d_out, int out_size) {
    const float* x   = (const float*)d_in[0];
    const void*  ei  = d_in[1];
    const float* W1  = (const float*)d_in[2];
    const float* as1 = (const float*)d_in[3];
    const float* ad1 = (const float*)d_in[4];
    const float* b1  = (const float*)d_in[5];
    const float* W2  = (const float*)d_in[6];
    const float* as2 = (const float*)d_in[7];
    const float* ad2 = (const float*)d_in[8];
    const float* b2  = (const float*)d_in[9];
    float* out = (float*)d_out;

    int N = in_sizes[0] / 128;
    int E = in_sizes[1] / 2;
    int tot = E + N;
    int nb = (N + 255) / 256;

    k_init<<<(N + 511) / 512, 512>>>((const int*)ei, in_sizes[1], N);

    dim3 g1(2, (N + 127) / 128);
    k_gemm1<<<g1, 256>>>(x, W1, as1, ad1, N);

    k_hist<<<(tot + 255) / 256, 256>>>(ei, E, N);
    k_scan1<<<nb, 256>>>(N);
    k_scan2<<<1, 256>>>(nb);
    k_scan3<<<nb, 256>>>(N, tot);
    k_scatter<<<(tot + 255) / 256, 256>>>(ei, E, N);

    k_agg1<<<(N * 32 + 255) / 256, 256>>>(b1, N);
    k_gemm2<<<(N + 15) / 16, 256>>>(W2, as2, ad2, N);
    k_agg2<<<(N * 32 + 255) / 256, 256>>>(b2, out, N);
}

// round 7
// speedup vs baseline: 1.6675x; 1.1190x over previous
#include <cuda_runtime.h>
#include <cuda_fp16.h>
#include <cstdint>

#define NMAX 50000
#define EMAX 800000
#define ETOTMAX (NMAX + EMAX)

// ---------------- scratch (device globals; no allocation allowed) ----------
__device__ __half g_h1h[NMAX * 256];   // layer-1 features (fp16, for gather)
__device__ __half g_w1t[256 * 128];    // W1 transposed [n,k] fp16
__device__ float g_hagg[NMAX * 256];   // layer-1 aggregated output (+bias1, pre-ELU)
__device__ float g_asrc1[NMAX * 8];
__device__ float g_adst1[NMAX * 8];
__device__ float g_h2[NMAX * 16];
__device__ float g_asrc2[NMAX];
__device__ float g_adst2[NMAX];
__device__ int   g_cnt[NMAX];
__device__ int   g_off[NMAX + 1];
__device__ int   g_cur[NMAX];
__device__ int   g_csr[ETOTMAX];
__device__ int   g_bsum[256];
__device__ int   g_is64;

__device__ __forceinline__ float lrelu(float x) { return x > 0.f ? x : 0.2f * x; }
__device__ __forceinline__ float warp_sum(float v) {
    #pragma unroll
    for (int o = 16; o; o >>= 1) v += __shfl_xor_sync(0xffffffffu, v, o);
    return v;
}
__device__ __forceinline__ float warp_max(float v) {
    #pragma unroll
    for (int o = 16; o; o >>= 1) v = fmaxf(v, __shfl_xor_sync(0xffffffffu, v, o));
    return v;
}

__device__ __forceinline__ uint32_t smem_u32(const void* p) {
    uint32_t a;
    asm("{ .reg .u64 t; cvta.to.shared.u64 t, %1; cvt.u32.u64 %0, t; }"
        : "=r"(a) : "l"(p));
    return a;
}

// ---------------- init: zero counters + detect dtype + W1->fp16^T ----------
__global__ void k_init(const int* __restrict__ ei32, int twoE, int N,
                       const float* __restrict__ W1) {
    int i = blockIdx.x * blockDim.x + threadIdx.x;
    if (i < N) g_cnt[i] = 0;
    if (i < 256 * 128) {
        int n = i >> 7, k = i & 127;
        g_w1t[i] = __float2half(W1[k * 256 + n]);
    }
    if (blockIdx.x == 0) {
        __shared__ int s_any;
        if (threadIdx.x == 0) s_any = 0;
        __syncthreads();
        int n = twoE < 2048 ? twoE : 2048;
        int nz = 0;
        for (int j = 2 * (int)threadIdx.x + 1; j < n; j += 2048)
            nz |= (ei32[j] != 0);
        if (nz) atomicOr(&s_any, 1);
        __syncthreads();
        if (threadIdx.x == 0) g_is64 = s_any ? 0 : 1;
    }
}

// ---------------- GEMM1 via mma.sync (HMMA) + fused att logits -------------
// 256 threads (8 warps), tile 128 rows x 128 cols, K=128 single stage.
// smem: A fp16 [128][136], B fp16 [128][136]; C fp32 [128][132] reuses A/B.
#define LDA 136
#define LDC 132
#define SM_A   0
#define SM_B   (128 * LDA * 2)                 // 34816
#define SM_ATT (2 * 128 * LDA * 2)             // 69632
#define SM_TOT (SM_ATT + 2048)

__device__ __forceinline__ void ldsm4(uint32_t* r, uint32_t addr) {
    asm volatile("ldmatrix.sync.aligned.m8n8.x4.shared.b16 {%0,%1,%2,%3}, [%4];"
                 : "=r"(r[0]), "=r"(r[1]), "=r"(r[2]), "=r"(r[3]) : "r"(addr));
}
__device__ __forceinline__ void mma16816(float* c, const uint32_t* a, const uint32_t* b) {
    asm volatile(
        "mma.sync.aligned.m16n8k16.row.col.f32.f16.f16.f32 "
        "{%0,%1,%2,%3}, {%4,%5,%6,%7}, {%8,%9}, {%0,%1,%2,%3};"
        : "+f"(c[0]), "+f"(c[1]), "+f"(c[2]), "+f"(c[3])
        : "r"(a[0]), "r"(a[1]), "r"(a[2]), "r"(a[3]), "r"(b[0]), "r"(b[1]));
}

__global__ __launch_bounds__(256) void k_gemm1(const float* __restrict__ A,
                                               const float* __restrict__ att_s,
                                               const float* __restrict__ att_d,
                                               int M) {
    extern __shared__ char smem[];
    uint32_t sb = smem_u32(smem);
    __half* As = (__half*)(smem + SM_A);
    __half* Bs = (__half*)(smem + SM_B);
    float* Cs = (float*)(smem + SM_A);
    float* sas = (float*)(smem + SM_ATT);
    float* sad = (float*)(smem + SM_ATT + 1024);

    int tid = threadIdx.x;
    int wid = tid >> 5, lane = tid & 31;
    int row0 = blockIdx.y * 128, col0 = blockIdx.x * 128;

    // att vectors -> smem
    for (int i = tid; i < 256; i += 256) {
        sas[i] = att_s[i];
        sad[i] = att_d[i];
    }

    // A tile: fp32 -> fp16, rows [row0,row0+128) x K=128
    for (int i = tid; i < 128 * 16; i += 256) {
        int r = i >> 4, c8 = (i & 15) * 8;
        int gr = row0 + r;
        float4 f0 = make_float4(0.f, 0.f, 0.f, 0.f), f1 = f0;
        if (gr < M) {
            f0 = *(const float4*)&A[(size_t)gr * 128 + c8];
            f1 = *(const float4*)&A[(size_t)gr * 128 + c8 + 4];
        }
        __half2 h0 = __floats2half2_rn(f0.x, f0.y);
        __half2 h1 = __floats2half2_rn(f0.z, f0.w);
        __half2 h2 = __floats2half2_rn(f1.x, f1.y);
        __half2 h3 = __floats2half2_rn(f1.z, f1.w);
        uint4 pk;
        pk.x = *(unsigned*)&h0; pk.y = *(unsigned*)&h1;
        pk.z = *(unsigned*)&h2; pk.w = *(unsigned*)&h3;
        *(uint4*)&As[r * LDA + c8] = pk;
    }
    // B tile: g_w1t[n][k] fp16, n in [col0,col0+128)
    for (int i = tid; i < 128 * 16; i += 256) {
        int n = i >> 4, c8 = (i & 15) * 8;
        uint4 pk = *(const uint4*)&g_w1t[(size_t)(col0 + n) * 128 + c8];
        *(uint4*)&Bs[n * LDA + c8] = pk;
    }
    __syncthreads();

    // warp layout: wm = wid&3 (rows wm*32..+32), wn = wid>>2 (cols wn*64..+64)
    int wm = wid & 3, wn = wid >> 2;
    int m0w = wm * 32, n0w = wn * 64;

    float acc[2][8][4];
    #pragma unroll
    for (int mi = 0; mi < 2; mi++)
        #pragma unroll
        for (int ni = 0; ni < 8; ni++)
            #pragma unroll
            for (int q = 0; q < 4; q++) acc[mi][ni][q] = 0.f;

    // lane-derived base addresses (bytes)
    uint32_t aRow = (uint32_t)(m0w + (lane & 7) + ((lane >> 3) & 1) * 8);
    uint32_t aK   = (uint32_t)((lane >> 4) * 8);
    uint32_t aBase = sb + SM_A + (aRow * LDA + aK) * 2;
    uint32_t bRow = (uint32_t)(n0w + (lane >> 4) * 8 + (lane & 7));
    uint32_t bK   = (uint32_t)(((lane >> 3) & 1) * 8);
    uint32_t bBase = sb + SM_B + (bRow * LDA + bK) * 2;

    #pragma unroll
    for (int ks = 0; ks < 8; ks++) {
        uint32_t k0b = ks * 16 * 2;
        uint32_t af[2][4];
        ldsm4(af[0], aBase + k0b);
        ldsm4(af[1], aBase + k0b + 16 * LDA * 2);
        uint32_t bf[8][2];
        #pragma unroll
        for (int np = 0; np < 4; np++) {
            uint32_t r4[4];
            ldsm4(r4, bBase + k0b + np * 16 * LDA * 2);
            bf[2 * np][0] = r4[0]; bf[2 * np][1] = r4[1];
            bf[2 * np + 1][0] = r4[2]; bf[2 * np + 1][1] = r4[3];
        }
        #pragma unroll
        for (int mi = 0; mi < 2; mi++)
            #pragma unroll
            for (int ni = 0; ni < 8; ni++)
                mma16816(acc[mi][ni], af[mi], bf[ni]);
    }
    __syncthreads();   // done reading A/B; reuse as C

    // write accumulators to smem C [128][132]
    int g = lane >> 2, tig = lane & 3;
    #pragma unroll
    for (int mi = 0; mi < 2; mi++) {
        #pragma unroll
        for (int ni = 0; ni < 8; ni++) {
            int r = m0w + mi * 16 + g;
            int c = n0w + ni * 8 + tig * 2;
            float2 lo = make_float2(acc[mi][ni][0], acc[mi][ni][1]);
            float2 hi = make_float2(acc[mi][ni][2], acc[mi][ni][3]);
            *(float2*)&Cs[r * LDC + c] = lo;
            *(float2*)&Cs[(r + 8) * LDC + c] = hi;
        }
    }
    __syncthreads();

    // epilogue: thread r = tid&127, half = tid>>7 owns 64 cols = 2 heads
    int r = tid & 127, half = tid >> 7;
    int grow = row0 + r;
    if (grow < M) {
        int cl0 = half * 64;                 // local col base
        int hb = (col0 >> 5) + half * 2;     // first global head
        float ps0 = 0.f, pd0 = 0.f, ps1 = 0.f, pd1 = 0.f;
        __half2 hh[32];
        #pragma unroll
        for (int j = 0; j < 16; j++) {
            float4 v = *(const float4*)&Cs[r * LDC + cl0 + j * 4];
            int gc = col0 + cl0 + j * 4;
            if (j < 8) {
                ps0 = fmaf(v.x, sas[gc], fmaf(v.y, sas[gc + 1],
                      fmaf(v.z, sas[gc + 2], fmaf(v.w, sas[gc + 3], ps0))));
                pd0 = fmaf(v.x, sad[gc], fmaf(v.y, sad[gc + 1],
                      fmaf(v.z, sad[gc + 2], fmaf(v.w, sad[gc + 3], pd0))));
            } else {
                ps1 = fmaf(v.x, sas[gc], fmaf(v.y, sas[gc + 1],
                      fmaf(v.z, sas[gc + 2], fmaf(v.w, sas[gc + 3], ps1))));
                pd1 = fmaf(v.x, sad[gc], fmaf(v.y, sad[gc + 1],
                      fmaf(v.z, sad[gc + 2], fmaf(v.w, sad[gc + 3], pd1))));
            }
            hh[j * 2] = __floats2half2_rn(v.x, v.y);
            hh[j * 2 + 1] = __floats2half2_rn(v.z, v.w);
        }
        g_asrc1[grow * 8 + hb] = ps0;
        g_adst1[grow * 8 + hb] = pd0;
        g_asrc1[grow * 8 + hb + 1] = ps1;
        g_adst1[grow * 8 + hb + 1] = pd1;
        uint4* dst = (uint4*)&g_h1h[(size_t)grow * 256 + col0 + cl0];
        #pragma unroll
        for (int q = 0; q < 8; q++) {
            uint4 pk;
            pk.x = *(unsigned*)&hh[q * 4 + 0];
            pk.y = *(unsigned*)&hh[q * 4 + 1];
            pk.z = *(unsigned*)&hh[q * 4 + 2];
            pk.w = *(unsigned*)&hh[q * 4 + 3];
            dst[q] = pk;
        }
    }
}

// ---------------- CSR build -------------------------------------------------
__global__ void k_hist(const void* __restrict__ ei, int E, int N) {
    int i = blockIdx.x * blockDim.x + threadIdx.x;
    if (i >= E + N) return;
    int d;
    if (i < E) {
        d = g_is64 ? (int)((const long long*)ei)[E + i]
                   : ((const int*)ei)[E + i];
    } else {
        d = i - E;
    }
    atomicAdd(&g_cnt[d], 1);
}

__global__ __launch_bounds__(256) void k_scan1(int N) {
    __shared__ int sd[256];
    int i = blockIdx.x * 256 + threadIdx.x;
    int v = (i < N) ? g_cnt[i] : 0;
    sd[threadIdx.x] = v;
    __syncthreads();
    #pragma unroll
    for (int s = 1; s < 256; s <<= 1) {
        int t = (threadIdx.x >= s) ? sd[threadIdx.x - s] : 0;
        __syncthreads();
        sd[threadIdx.x] += t;
        __syncthreads();
    }
    if (i < N) g_off[i] = sd[threadIdx.x] - v;
    if (threadIdx.x == 255) g_bsum[blockIdx.x] = sd[255];
}

__global__ __launch_bounds__(256) void k_scan2(int nb) {
    __shared__ int sd[256];
    int v = (threadIdx.x < nb) ? g_bsum[threadIdx.x] : 0;
    sd[threadIdx.x] = v;
    __syncthreads();
    #pragma unroll
    for (int s = 1; s < 256; s <<= 1) {
        int t = (threadIdx.x >= s) ? sd[threadIdx.x - s] : 0;
        __syncthreads();
        sd[threadIdx.x] += t;
        __syncthreads();
    }
    if (threadIdx.x < nb) g_bsum[threadIdx.x] = sd[threadIdx.x] - v;
}

__global__ __launch_bounds__(256) void k_scan3(int N, int total) {
    int i = blockIdx.x * 256 + threadIdx.x;
    if (i < N) {
        int o = g_off[i] + g_bsum[blockIdx.x];
        g_off[i] = o;
        g_cur[i] = o;
    }
    if (i == 0) g_off[N] = total;
}

__global__ void k_scatter(const void* __restrict__ ei, int E, int N) {
    int i = blockIdx.x * blockDim.x + threadIdx.x;
    if (i >= E + N) return;
    int s, d;
    if (i < E) {
        if (g_is64) {
            const long long* p = (const long long*)ei;
            s = (int)p[i]; d = (int)p[E + i];
        } else {
            const int* p = (const int*)ei;
            s = p[i]; d = p[E + i];
        }
    } else {
        s = d = i - E;
    }
    int pos = atomicAdd(&g_cur[d], 1);
    g_csr[pos] = s;
}

// ---------------- layer-1 softmax + aggregation (warp per dst) -------------
__global__ __launch_bounds__(256) void k_agg1(const float* __restrict__ bias1, int N) {
    int d = (blockIdx.x * blockDim.x + threadIdx.x) >> 5;
    int lane = threadIdx.x & 31;
    if (d >= N) return;
    int beg = g_off[d], end = g_off[d + 1];
    int h = lane & 7, eg = lane >> 3;
    float adv = g_adst1[d * 8 + h];

    float m = -1e30f;
    for (int e = beg + eg; e < end; e += 4)
        m = fmaxf(m, lrelu(g_asrc1[g_csr[e] * 8 + h] + adv));
    m = fmaxf(m, __shfl_xor_sync(0xffffffffu, m, 8));
    m = fmaxf(m, __shfl_xor_sync(0xffffffffu, m, 16));

    float sum = 0.f;
    for (int e = beg + eg; e < end; e += 4)
        sum += __expf(lrelu(g_asrc1[g_csr[e] * 8 + h] + adv) - m);
    sum += __shfl_xor_sync(0xffffffffu, sum, 8);
    sum += __shfl_xor_sync(0xffffffffu, sum, 16);
    float inv = 1.f / (sum + 1e-16f);

    float2 acc[4];
    #pragma unroll
    for (int j = 0; j < 4; j++) acc[j] = make_float2(0.f, 0.f);
    int hj[4];
    #pragma unroll
    for (int j = 0; j < 4; j++) hj[j] = j * 2 + (lane >> 4);

    const __half2* base = (const __half2*)g_h1h;
    for (int e = beg; e < end; e++) {
        int s = g_csr[e];
        float w = 0.f;
        if (lane < 8)
            w = __expf(lrelu(g_asrc1[s * 8 + lane] + adv) - m) * inv;
        const __half2* hp = base + (size_t)s * 128 + lane;
        #pragma unroll
        for (int j = 0; j < 4; j++) {
            float wj = __shfl_sync(0xffffffffu, w, hj[j]);
            float2 f = __half22float2(hp[j * 32]);
            acc[j].x = fmaf(f.x, wj, acc[j].x);
            acc[j].y = fmaf(f.y, wj, acc[j].y);
        }
    }
    float* op = g_hagg + (size_t)d * 256;
    #pragma unroll
    for (int j = 0; j < 4; j++) {
        int c = j * 64 + lane * 2;
        float2 bv = *(const float2*)&bias1[c];
        float2 o = make_float2(acc[j].x + bv.x, acc[j].y + bv.y);
        *(float2*)&op[c] = o;
    }
}

// ---------------- GEMM2 (elu on the fly) + layer-2 logits ------------------
__global__ __launch_bounds__(256) void k_gemm2(const float* __restrict__ W2,
                                               const float* __restrict__ as2,
                                               const float* __restrict__ ad2, int N) {
    __shared__ float sh[16][260];
    __shared__ float sw[256 * 16];
    int tid = threadIdx.x;
    int row = tid >> 4, col = tid & 15;
    int n0 = blockIdx.x * 16;

    #pragma unroll
    for (int i = 0; i < 16; i++) sw[tid + i * 256] = W2[tid + i * 256];
    for (int i = tid; i < 16 * 256; i += 256) {
        int r = i >> 8, c = i & 255;
        int n = n0 + r;
        float v = (n < N) ? g_hagg[(size_t)n * 256 + c] : 0.f;
        sh[r][c] = v > 0.f ? v : expm1f(v);
    }
    __syncthreads();

    float acc = 0.f;
    #pragma unroll 8
    for (int k = 0; k < 256; k++) acc = fmaf(sh[row][k], sw[k * 16 + col], acc);

    float ps = acc * as2[col];
    float pd = acc * ad2[col];
    #pragma unroll
    for (int o = 8; o; o >>= 1) {
        ps += __shfl_xor_sync(0xffffffffu, ps, o);
        pd += __shfl_xor_sync(0xffffffffu, pd, o);
    }
    int n = n0 + row;
    if (n < N) {
        g_h2[n * 16 + col] = acc;
        if (col == 0) { g_asrc2[n] = ps; g_adst2[n] = pd; }
    }
}

// ---------------- layer-2 softmax + aggregation (warp per dst) -------------
__global__ __launch_bounds__(256) void k_agg2(const float* __restrict__ bias2,
                                              float* __restrict__ out, int N) {
    int d = (blockIdx.x * blockDim.x + threadIdx.x) >> 5;
    int lane = threadIdx.x & 31;
    if (d >= N) return;
    int beg = g_off[d], end = g_off[d + 1];
    float ad = g_adst2[d];

    float m = -1e30f;
    for (int e = beg + lane; e < end; e += 32)
        m = fmaxf(m, lrelu(g_asrc2[g_csr[e]] + ad));
    m = warp_max(m);

    float sum = 0.f;
    for (int e = beg + lane; e < end; e += 32)
        sum += __expf(lrelu(g_asrc2[g_csr[e]] + ad) - m);
    sum = warp_sum(sum);
    float inv = 1.f / (sum + 1e-16f);

    float acc = 0.f;
    for (int e = beg; e < end; e++) {
        int s = g_csr[e];
        float w = 0.f;
        if (lane == 0) w = __expf(lrelu(g_asrc2[s] + ad) - m) * inv;
        w = __shfl_sync(0xffffffffu, w, 0);
        if (lane < 16) acc = fmaf(g_h2[s * 16 + lane], w, acc);
    }
    if (lane < 16) out[d * 16 + lane] = acc + bias2[lane];
}

// ---------------- launch ----------------------------------------------------
extern "C" void kernel_launch(void* const* d_in, const int* in_sizes, int n_in,
                              void* d_out, int out_size) {
    const float* x   = (const float*)d_in[0];
    const void*  ei  = d_in[1];
    const float* W1  = (const float*)d_in[2];
    const float* as1 = (const float*)d_in[3];
    const float* ad1 = (const float*)d_in[4];
    const float* b1  = (const float*)d_in[5];
    const float* W2  = (const float*)d_in[6];
    const float* as2 = (const float*)d_in[7];
    const float* ad2 = (const float*)d_in[8];
    const float* b2  = (const float*)d_in[9];
    float* out = (float*)d_out;

    int N = in_sizes[0] / 128;
    int E = in_sizes[1] / 2;
    int tot = E + N;
    int nb = (N + 255) / 256;

    k_init<<<(N + 1023) / 1024, 1024>>>((const int*)ei, in_sizes[1], N, W1);

    cudaFuncSetAttribute(k_gemm1, cudaFuncAttributeMaxDynamicSharedMemorySize, SM_TOT);
    dim3 g1(2, (N + 127) / 128);
    k_gemm1<<<g1, 256, SM_TOT>>>(x, as1, ad1, N);

    k_hist<<<(tot + 255) / 256, 256>>>(ei, E, N);
    k_scan1<<<nb, 256>>>(N);
    k_scan2<<<1, 256>>>(nb);
    k_scan3<<<nb, 256>>>(N, tot);
    k_scatter<<<(tot + 255) / 256, 256>>>(ei, E, N);

    k_agg1<<<(N * 32 + 255) / 256, 256>>>(b1, N);
    k_gemm2<<<(N + 15) / 16, 256>>>(W2, as2, ad2, N);
    k_agg2<<<(N * 32 + 255) / 256, 256>>>(b2, out, N);
}

// round 8
// speedup vs baseline: 2.0766x; 1.2454x over previous
#include <cuda_runtime.h>
#include <cuda_fp16.h>
#include <cstdint>

#define NMAX 50000
#define EMAX 800000
#define ETOTMAX (NMAX + EMAX)

// ---------------- scratch (device globals; no allocation allowed) ----------
__device__ __half g_h1h[NMAX * 256];   // layer-1 features (fp16, for gather)
__device__ __half g_xh[NMAX * 128];    // x converted to fp16
__device__ __half g_w1t[256 * 128];    // W1 transposed [n,k] fp16
__device__ float g_asrc1[NMAX * 8];
__device__ float g_adst1[NMAX * 8];
__device__ float g_h2[NMAX * 16];
__device__ float g_asrc2[NMAX];
__device__ float g_adst2[NMAX];
__device__ int   g_cnt[NMAX];
__device__ int   g_off[NMAX + 1];
__device__ int   g_cur[NMAX];
__device__ int   g_csr[ETOTMAX];
__device__ int   g_bsum[256];
__device__ int   g_is64;

__device__ __forceinline__ float lrelu(float x) { return x > 0.f ? x : 0.2f * x; }
__device__ __forceinline__ float warp_sum(float v) {
    #pragma unroll
    for (int o = 16; o; o >>= 1) v += __shfl_xor_sync(0xffffffffu, v, o);
    return v;
}
__device__ __forceinline__ float warp_max(float v) {
    #pragma unroll
    for (int o = 16; o; o >>= 1) v = fmaxf(v, __shfl_xor_sync(0xffffffffu, v, o));
    return v;
}

__device__ __forceinline__ uint32_t smem_u32(const void* p) {
    uint32_t a;
    asm("{ .reg .u64 t; cvta.to.shared.u64 t, %1; cvt.u32.u64 %0, t; }"
        : "=r"(a) : "l"(p));
    return a;
}

// ------- init: zero counters + dtype detect + W1->fp16^T + x->fp16 ---------
__global__ void k_init(const int* __restrict__ ei32, int twoE, int N,
                       const float* __restrict__ W1,
                       const float* __restrict__ x) {
    int i = blockIdx.x * blockDim.x + threadIdx.x;
    int nt = gridDim.x * blockDim.x;
    if (i < N) g_cnt[i] = 0;
    if (i < 256 * 128) {
        int n = i >> 7, k = i & 127;
        g_w1t[i] = __float2half(W1[k * 256 + n]);
    }
    // x -> fp16, 4 elems per iter
    int quads = N * 32;   // N*128/4
    for (int q = i; q < quads; q += nt) {
        float4 f = *(const float4*)&x[(size_t)q * 4];
        __half2 h0 = __floats2half2_rn(f.x, f.y);
        __half2 h1 = __floats2half2_rn(f.z, f.w);
        uint2 pk;
        pk.x = *(unsigned*)&h0; pk.y = *(unsigned*)&h1;
        *(uint2*)&g_xh[(size_t)q * 4] = pk;
    }
    if (blockIdx.x == 0) {
        __shared__ int s_any;
        if (threadIdx.x == 0) s_any = 0;
        __syncthreads();
        int n = twoE < 2048 ? twoE : 2048;
        int nz = 0;
        for (int j = 2 * (int)threadIdx.x + 1; j < n; j += 2048)
            nz |= (ei32[j] != 0);
        if (nz) atomicOr(&s_any, 1);
        __syncthreads();
        if (threadIdx.x == 0) g_is64 = s_any ? 0 : 1;
    }
}

// ---------------- GEMM1 via mma.sync (HMMA) + fused att logits -------------
#define LDA 136
#define LDC 132
#define SM_A   0
#define SM_B   (128 * LDA * 2)
#define SM_ATT (2 * 128 * LDA * 2)
#define SM_TOT (SM_ATT + 2048)

__device__ __forceinline__ void ldsm4(uint32_t* r, uint32_t addr) {
    asm volatile("ldmatrix.sync.aligned.m8n8.x4.shared.b16 {%0,%1,%2,%3}, [%4];"
                 : "=r"(r[0]), "=r"(r[1]), "=r"(r[2]), "=r"(r[3]) : "r"(addr));
}
__device__ __forceinline__ void mma16816(float* c, const uint32_t* a, const uint32_t* b) {
    asm volatile(
        "mma.sync.aligned.m16n8k16.row.col.f32.f16.f16.f32 "
        "{%0,%1,%2,%3}, {%4,%5,%6,%7}, {%8,%9}, {%0,%1,%2,%3};"
        : "+f"(c[0]), "+f"(c[1]), "+f"(c[2]), "+f"(c[3])
        : "r"(a[0]), "r"(a[1]), "r"(a[2]), "r"(a[3]), "r"(b[0]), "r"(b[1]));
}

__global__ __launch_bounds__(256) void k_gemm1(const float* __restrict__ att_s,
                                               const float* __restrict__ att_d,
                                               int M) {
    extern __shared__ char smem[];
    uint32_t sb = smem_u32(smem);
    __half* As = (__half*)(smem + SM_A);
    __half* Bs = (__half*)(smem + SM_B);
    float* Cs = (float*)(smem + SM_A);
    float* sas = (float*)(smem + SM_ATT);
    float* sad = (float*)(smem + SM_ATT + 1024);

    int tid = threadIdx.x;
    int wid = tid >> 5, lane = tid & 31;
    int row0 = blockIdx.y * 128, col0 = blockIdx.x * 128;

    for (int i = tid; i < 256; i += 256) {
        sas[i] = att_s[i];
        sad[i] = att_d[i];
    }

    // A tile: fp16 x rows [row0,row0+128) x K=128
    for (int i = tid; i < 128 * 16; i += 256) {
        int r = i >> 4, c8 = (i & 15) * 8;
        int gr = row0 + r;
        uint4 pk = make_uint4(0u, 0u, 0u, 0u);
        if (gr < M) pk = *(const uint4*)&g_xh[(size_t)gr * 128 + c8];
        *(uint4*)&As[r * LDA + c8] = pk;
    }
    // B tile: g_w1t[n][k] fp16, n in [col0,col0+128)
    for (int i = tid; i < 128 * 16; i += 256) {
        int n = i >> 4, c8 = (i & 15) * 8;
        uint4 pk = *(const uint4*)&g_w1t[(size_t)(col0 + n) * 128 + c8];
        *(uint4*)&Bs[n * LDA + c8] = pk;
    }
    __syncthreads();

    int wm = wid & 3, wn = wid >> 2;
    int m0w = wm * 32, n0w = wn * 64;

    float acc[2][8][4];
    #pragma unroll
    for (int mi = 0; mi < 2; mi++)
        #pragma unroll
        for (int ni = 0; ni < 8; ni++)
            #pragma unroll
            for (int q = 0; q < 4; q++) acc[mi][ni][q] = 0.f;

    uint32_t aRow = (uint32_t)(m0w + (lane & 7) + ((lane >> 3) & 1) * 8);
    uint32_t aK   = (uint32_t)((lane >> 4) * 8);
    uint32_t aBase = sb + SM_A + (aRow * LDA + aK) * 2;
    uint32_t bRow = (uint32_t)(n0w + (lane >> 4) * 8 + (lane & 7));
    uint32_t bK   = (uint32_t)(((lane >> 3) & 1) * 8);
    uint32_t bBase = sb + SM_B + (bRow * LDA + bK) * 2;

    #pragma unroll
    for (int ks = 0; ks < 8; ks++) {
        uint32_t k0b = ks * 16 * 2;
        uint32_t af[2][4];
        ldsm4(af[0], aBase + k0b);
        ldsm4(af[1], aBase + k0b + 16 * LDA * 2);
        uint32_t bf[8][2];
        #pragma unroll
        for (int np = 0; np < 4; np++) {
            uint32_t r4[4];
            ldsm4(r4, bBase + k0b + np * 16 * LDA * 2);
            bf[2 * np][0] = r4[0]; bf[2 * np][1] = r4[1];
            bf[2 * np + 1][0] = r4[2]; bf[2 * np + 1][1] = r4[3];
        }
        #pragma unroll
        for (int mi = 0; mi < 2; mi++)
            #pragma unroll
            for (int ni = 0; ni < 8; ni++)
                mma16816(acc[mi][ni], af[mi], bf[ni]);
    }
    __syncthreads();

    int g = lane >> 2, tig = lane & 3;
    #pragma unroll
    for (int mi = 0; mi < 2; mi++) {
        #pragma unroll
        for (int ni = 0; ni < 8; ni++) {
            int r = m0w + mi * 16 + g;
            int c = n0w + ni * 8 + tig * 2;
            float2 lo = make_float2(acc[mi][ni][0], acc[mi][ni][1]);
            float2 hi = make_float2(acc[mi][ni][2], acc[mi][ni][3]);
            *(float2*)&Cs[r * LDC + c] = lo;
            *(float2*)&Cs[(r + 8) * LDC + c] = hi;
        }
    }
    __syncthreads();

    int r = tid & 127, half = tid >> 7;
    int grow = row0 + r;
    if (grow < M) {
        int cl0 = half * 64;
        int hb = (col0 >> 5) + half * 2;
        float ps0 = 0.f, pd0 = 0.f, ps1 = 0.f, pd1 = 0.f;
        __half2 hh[32];
        #pragma unroll
        for (int j = 0; j < 16; j++) {
            float4 v = *(const float4*)&Cs[r * LDC + cl0 + j * 4];
            int gc = col0 + cl0 + j * 4;
            if (j < 8) {
                ps0 = fmaf(v.x, sas[gc], fmaf(v.y, sas[gc + 1],
                      fmaf(v.z, sas[gc + 2], fmaf(v.w, sas[gc + 3], ps0))));
                pd0 = fmaf(v.x, sad[gc], fmaf(v.y, sad[gc + 1],
                      fmaf(v.z, sad[gc + 2], fmaf(v.w, sad[gc + 3], pd0))));
            } else {
                ps1 = fmaf(v.x, sas[gc], fmaf(v.y, sas[gc + 1],
                      fmaf(v.z, sas[gc + 2], fmaf(v.w, sas[gc + 3], ps1))));
                pd1 = fmaf(v.x, sad[gc], fmaf(v.y, sad[gc + 1],
                      fmaf(v.z, sad[gc + 2], fmaf(v.w, sad[gc + 3], pd1))));
            }
            hh[j * 2] = __floats2half2_rn(v.x, v.y);
            hh[j * 2 + 1] = __floats2half2_rn(v.z, v.w);
        }
        g_asrc1[grow * 8 + hb] = ps0;
        g_adst1[grow * 8 + hb] = pd0;
        g_asrc1[grow * 8 + hb + 1] = ps1;
        g_adst1[grow * 8 + hb + 1] = pd1;
        uint4* dst = (uint4*)&g_h1h[(size_t)grow * 256 + col0 + cl0];
        #pragma unroll
        for (int q = 0; q < 8; q++) {
            uint4 pk;
            pk.x = *(unsigned*)&hh[q * 4 + 0];
            pk.y = *(unsigned*)&hh[q * 4 + 1];
            pk.z = *(unsigned*)&hh[q * 4 + 2];
            pk.w = *(unsigned*)&hh[q * 4 + 3];
            dst[q] = pk;
        }
    }
}

// ---------------- CSR build -------------------------------------------------
__global__ void k_hist(const void* __restrict__ ei, int E, int N) {
    int i = blockIdx.x * blockDim.x + threadIdx.x;
    if (i >= E + N) return;
    int d;
    if (i < E) {
        d = g_is64 ? (int)((const long long*)ei)[E + i]
                   : ((const int*)ei)[E + i];
    } else {
        d = i - E;
    }
    atomicAdd(&g_cnt[d], 1);
}

__global__ __launch_bounds__(256) void k_scan1(int N) {
    __shared__ int sd[256];
    int i = blockIdx.x * 256 + threadIdx.x;
    int v = (i < N) ? g_cnt[i] : 0;
    sd[threadIdx.x] = v;
    __syncthreads();
    #pragma unroll
    for (int s = 1; s < 256; s <<= 1) {
        int t = (threadIdx.x >= s) ? sd[threadIdx.x - s] : 0;
        __syncthreads();
        sd[threadIdx.x] += t;
        __syncthreads();
    }
    if (i < N) g_off[i] = sd[threadIdx.x] - v;
    if (threadIdx.x == 255) g_bsum[blockIdx.x] = sd[255];
}

__global__ __launch_bounds__(256) void k_scan2(int nb) {
    __shared__ int sd[256];
    int v = (threadIdx.x < nb) ? g_bsum[threadIdx.x] : 0;
    sd[threadIdx.x] = v;
    __syncthreads();
    #pragma unroll
    for (int s = 1; s < 256; s <<= 1) {
        int t = (threadIdx.x >= s) ? sd[threadIdx.x - s] : 0;
        __syncthreads();
        sd[threadIdx.x] += t;
        __syncthreads();
    }
    if (threadIdx.x < nb) g_bsum[threadIdx.x] = sd[threadIdx.x] - v;
}

__global__ __launch_bounds__(256) void k_scan3(int N, int total) {
    int i = blockIdx.x * 256 + threadIdx.x;
    if (i < N) {
        int o = g_off[i] + g_bsum[blockIdx.x];
        g_off[i] = o;
        g_cur[i] = o;
    }
    if (i == 0) g_off[N] = total;
}

__global__ void k_scatter(const void* __restrict__ ei, int E, int N) {
    int i = blockIdx.x * blockDim.x + threadIdx.x;
    if (i >= E + N) return;
    int s, d;
    if (i < E) {
        if (g_is64) {
            const long long* p = (const long long*)ei;
            s = (int)p[i]; d = (int)p[E + i];
        } else {
            const int* p = (const int*)ei;
            s = p[i]; d = p[E + i];
        }
    } else {
        s = d = i - E;
    }
    int pos = atomicAdd(&g_cur[d], 1);
    g_csr[pos] = s;
}

// ------- layer-1 softmax + aggregation + FUSED gemm2 + layer-2 logits ------
// warp per dst node; after aggregation, apply bias+ELU and compute
// h2[d] = elu(v) @ W2 (256x16) entirely in-warp (conflict-free smem GEMV).
__global__ __launch_bounds__(256) void k_agg1(const float* __restrict__ bias1,
                                              const float* __restrict__ W2,
                                              const float* __restrict__ as2,
                                              const float* __restrict__ ad2,
                                              int N) {
    __shared__ float w2s[4096];     // W2 [256][16]
    __shared__ float sv[8][256];    // per-warp elu'd feature vector

    for (int i = threadIdx.x; i < 4096; i += 256) w2s[i] = W2[i];
    __syncthreads();

    int d = (blockIdx.x * blockDim.x + threadIdx.x) >> 5;
    int lane = threadIdx.x & 31;
    int wid = threadIdx.x >> 5;
    if (d >= N) return;
    int beg = g_off[d], end = g_off[d + 1];
    int h = lane & 7, eg = lane >> 3;
    float adv = g_adst1[d * 8 + h];

    float m = -1e30f;
    for (int e = beg + eg; e < end; e += 4)
        m = fmaxf(m, lrelu(g_asrc1[g_csr[e] * 8 + h] + adv));
    m = fmaxf(m, __shfl_xor_sync(0xffffffffu, m, 8));
    m = fmaxf(m, __shfl_xor_sync(0xffffffffu, m, 16));

    float sum = 0.f;
    for (int e = beg + eg; e < end; e += 4)
        sum += __expf(lrelu(g_asrc1[g_csr[e] * 8 + h] + adv) - m);
    sum += __shfl_xor_sync(0xffffffffu, sum, 8);
    sum += __shfl_xor_sync(0xffffffffu, sum, 16);
    float inv = 1.f / (sum + 1e-16f);

    float2 acc[4];
    #pragma unroll
    for (int j = 0; j < 4; j++) acc[j] = make_float2(0.f, 0.f);
    int hj[4];
    #pragma unroll
    for (int j = 0; j < 4; j++) hj[j] = j * 2 + (lane >> 4);

    const __half2* base = (const __half2*)g_h1h;
    for (int e = beg; e < end; e++) {
        int s = g_csr[e];
        float w = 0.f;
        if (lane < 8)
            w = __expf(lrelu(g_asrc1[s * 8 + lane] + adv) - m) * inv;
        const __half2* hp = base + (size_t)s * 128 + lane;
        #pragma unroll
        for (int j = 0; j < 4; j++) {
            float wj = __shfl_sync(0xffffffffu, w, hj[j]);
            float2 f = __half22float2(hp[j * 32]);
            acc[j].x = fmaf(f.x, wj, acc[j].x);
            acc[j].y = fmaf(f.y, wj, acc[j].y);
        }
    }

    // bias + ELU -> sv
    #pragma unroll
    for (int j = 0; j < 4; j++) {
        int c = j * 64 + lane * 2;
        float2 bv = *(const float2*)&bias1[c];
        float vx = acc[j].x + bv.x;
        float vy = acc[j].y + bv.y;
        vx = vx > 0.f ? vx : expm1f(vx);
        vy = vy > 0.f ? vy : expm1f(vy);
        sv[wid][c] = vx;
        sv[wid][c + 1] = vy;
    }
    __syncwarp();

    // GEMV: lane (n = lane&15, half = lane>>4) over interleaved c = 2t+half.
    // w2s banks: even c rows -> banks {n}, odd c rows -> banks {16+n}: conflict-free.
    int n = lane & 15, half = lane >> 4;
    float yp = 0.f;
    #pragma unroll 8
    for (int t = 0; t < 128; t++) {
        int c = 2 * t + half;
        yp = fmaf(sv[wid][c], w2s[c * 16 + n], yp);
    }
    yp += __shfl_xor_sync(0xffffffffu, yp, 16);

    float ps = 0.f, pd = 0.f;
    if (lane < 16) {
        g_h2[d * 16 + lane] = yp;
        ps = yp * __ldg(&as2[lane]);
        pd = yp * __ldg(&ad2[lane]);
    }
    ps = warp_sum(ps);
    pd = warp_sum(pd);
    if (lane == 0) { g_asrc2[d] = ps; g_adst2[d] = pd; }
}

// ---------------- layer-2 softmax + aggregation (warp per dst) -------------
__global__ __launch_bounds__(256) void k_agg2(const float* __restrict__ bias2,
                                              float* __restrict__ out, int N) {
    int d = (blockIdx.x * blockDim.x + threadIdx.x) >> 5;
    int lane = threadIdx.x & 31;
    if (d >= N) return;
    int beg = g_off[d], end = g_off[d + 1];
    float ad = g_adst2[d];

    float m = -1e30f;
    for (int e = beg + lane; e < end; e += 32)
        m = fmaxf(m, lrelu(g_asrc2[g_csr[e]] + ad));
    m = warp_max(m);

    float sum = 0.f;
    for (int e = beg + lane; e < end; e += 32)
        sum += __expf(lrelu(g_asrc2[g_csr[e]] + ad) - m);
    sum = warp_sum(sum);
    float inv = 1.f / (sum + 1e-16f);

    float acc = 0.f;
    for (int e = beg; e < end; e++) {
        int s = g_csr[e];
        float w = 0.f;
        if (lane == 0) w = __expf(lrelu(g_asrc2[s] + ad) - m) * inv;
        w = __shfl_sync(0xffffffffu, w, 0);
        if (lane < 16) acc = fmaf(g_h2[s * 16 + lane], w, acc);
    }
    if (lane < 16) out[d * 16 + lane] = acc + bias2[lane];
}

// ---------------- launch ----------------------------------------------------
extern "C" void kernel_launch(void* const* d_in, const int* in_sizes, int n_in,
                              void* d_out, int out_size) {
    const float* x   = (const float*)d_in[0];
    const void*  ei  = d_in[1];
    const float* W1  = (const float*)d_in[2];
    const float* as1 = (const float*)d_in[3];
    const float* ad1 = (const float*)d_in[4];
    const float* b1  = (const float*)d_in[5];
    const float* W2  = (const float*)d_in[6];
    const float* as2 = (const float*)d_in[7];
    const float* ad2 = (const float*)d_in[8];
    const float* b2  = (const float*)d_in[9];
    float* out = (float*)d_out;

    int N = in_sizes[0] / 128;
    int E = in_sizes[1] / 2;
    int tot = E + N;
    int nb = (N + 255) / 256;

    k_init<<<196, 256>>>((const int*)ei, in_sizes[1], N, W1, x);

    cudaFuncSetAttribute(k_gemm1, cudaFuncAttributeMaxDynamicSharedMemorySize, SM_TOT);
    dim3 g1(2, (N + 127) / 128);
    k_gemm1<<<g1, 256, SM_TOT>>>(as1, ad1, N);

    k_hist<<<(tot + 255) / 256, 256>>>(ei, E, N);
    k_scan1<<<nb, 256>>>(N);
    k_scan2<<<1, 256>>>(nb);
    k_scan3<<<nb, 256>>>(N, tot);
    k_scatter<<<(tot + 255) / 256, 256>>>(ei, E, N);

    k_agg1<<<(N * 32 + 255) / 256, 256>>>(b1, W2, as2, ad2, N);
    k_agg2<<<(N * 32 + 255) / 256, 256>>>(b2, out, N);
}

// round 9
// speedup vs baseline: 2.2697x; 1.0930x over previous
#include <cuda_runtime.h>
#include <cuda_fp16.h>
#include <cstdint>

#define NMAX 50000
#define EMAX 800000
#define ETOTMAX (NMAX + EMAX)

// ---------------- scratch (device globals; no allocation allowed) ----------
__device__ __half g_h1h[NMAX * 256];   // layer-1 features (fp16, for gather)
__device__ __half g_xh[NMAX * 128];    // x converted to fp16
__device__ __half g_w1t[256 * 128];    // W1 transposed [n,k] fp16
__device__ float g_asrc1[NMAX * 8];
__device__ float g_adst1[NMAX * 8];
__device__ float g_h2[NMAX * 16];
__device__ float g_asrc2[NMAX];
__device__ float g_adst2[NMAX];
__device__ int   g_cnt[NMAX];
__device__ int   g_off[NMAX + 1];
__device__ int   g_cur[NMAX];
__device__ int   g_csr[ETOTMAX];
__device__ int   g_bsum[256];
__device__ int   g_is64;

__device__ __forceinline__ float lrelu(float x) { return x > 0.f ? x : 0.2f * x; }
__device__ __forceinline__ float warp_sum(float v) {
    #pragma unroll
    for (int o = 16; o; o >>= 1) v += __shfl_xor_sync(0xffffffffu, v, o);
    return v;
}

__device__ __forceinline__ uint32_t smem_u32(const void* p) {
    uint32_t a;
    asm("{ .reg .u64 t; cvta.to.shared.u64 t, %1; cvt.u32.u64 %0, t; }"
        : "=r"(a) : "l"(p));
    return a;
}

// ------- init: zero counters + dtype detect + W1->fp16^T + x->fp16 ---------
__global__ void k_init(const int* __restrict__ ei32, int twoE, int N,
                       const float* __restrict__ W1,
                       const float* __restrict__ x) {
    int i = blockIdx.x * blockDim.x + threadIdx.x;
    int nt = gridDim.x * blockDim.x;
    if (i < N) g_cnt[i] = 0;
    if (i < 256 * 128) {
        int n = i >> 7, k = i & 127;
        g_w1t[i] = __float2half(W1[k * 256 + n]);
    }
    int quads = N * 32;
    for (int q = i; q < quads; q += nt) {
        float4 f = *(const float4*)&x[(size_t)q * 4];
        __half2 h0 = __floats2half2_rn(f.x, f.y);
        __half2 h1 = __floats2half2_rn(f.z, f.w);
        uint2 pk;
        pk.x = *(unsigned*)&h0; pk.y = *(unsigned*)&h1;
        *(uint2*)&g_xh[(size_t)q * 4] = pk;
    }
    if (blockIdx.x == 0) {
        __shared__ int s_any;
        if (threadIdx.x == 0) s_any = 0;
        __syncthreads();
        int n = twoE < 2048 ? twoE : 2048;
        int nz = 0;
        for (int j = 2 * (int)threadIdx.x + 1; j < n; j += 2048)
            nz |= (ei32[j] != 0);
        if (nz) atomicOr(&s_any, 1);
        __syncthreads();
        if (threadIdx.x == 0) g_is64 = s_any ? 0 : 1;
    }
}

// ---------------- GEMM1 via mma.sync (HMMA) + fused att logits -------------
#define LDA 136
#define LDC 132
#define SM_A   0
#define SM_B   (128 * LDA * 2)
#define SM_ATT (2 * 128 * LDA * 2)
#define SM_TOT (SM_ATT + 2048)

__device__ __forceinline__ void ldsm4(uint32_t* r, uint32_t addr) {
    asm volatile("ldmatrix.sync.aligned.m8n8.x4.shared.b16 {%0,%1,%2,%3}, [%4];"
                 : "=r"(r[0]), "=r"(r[1]), "=r"(r[2]), "=r"(r[3]) : "r"(addr));
}
__device__ __forceinline__ void mma16816(float* c, const uint32_t* a, const uint32_t* b) {
    asm volatile(
        "mma.sync.aligned.m16n8k16.row.col.f32.f16.f16.f32 "
        "{%0,%1,%2,%3}, {%4,%5,%6,%7}, {%8,%9}, {%0,%1,%2,%3};"
        : "+f"(c[0]), "+f"(c[1]), "+f"(c[2]), "+f"(c[3])
        : "r"(a[0]), "r"(a[1]), "r"(a[2]), "r"(a[3]), "r"(b[0]), "r"(b[1]));
}

__global__ __launch_bounds__(256) void k_gemm1(const float* __restrict__ att_s,
                                               const float* __restrict__ att_d,
                                               int M) {
    extern __shared__ char smem[];
    uint32_t sb = smem_u32(smem);
    __half* As = (__half*)(smem + SM_A);
    __half* Bs = (__half*)(smem + SM_B);
    float* Cs = (float*)(smem + SM_A);
    float* sas = (float*)(smem + SM_ATT);
    float* sad = (float*)(smem + SM_ATT + 1024);

    int tid = threadIdx.x;
    int wid = tid >> 5, lane = tid & 31;
    int row0 = blockIdx.y * 128, col0 = blockIdx.x * 128;

    for (int i = tid; i < 256; i += 256) {
        sas[i] = att_s[i];
        sad[i] = att_d[i];
    }

    for (int i = tid; i < 128 * 16; i += 256) {
        int r = i >> 4, c8 = (i & 15) * 8;
        int gr = row0 + r;
        uint4 pk = make_uint4(0u, 0u, 0u, 0u);
        if (gr < M) pk = *(const uint4*)&g_xh[(size_t)gr * 128 + c8];
        *(uint4*)&As[r * LDA + c8] = pk;
    }
    for (int i = tid; i < 128 * 16; i += 256) {
        int n = i >> 4, c8 = (i & 15) * 8;
        uint4 pk = *(const uint4*)&g_w1t[(size_t)(col0 + n) * 128 + c8];
        *(uint4*)&Bs[n * LDA + c8] = pk;
    }
    __syncthreads();

    int wm = wid & 3, wn = wid >> 2;
    int m0w = wm * 32, n0w = wn * 64;

    float acc[2][8][4];
    #pragma unroll
    for (int mi = 0; mi < 2; mi++)
        #pragma unroll
        for (int ni = 0; ni < 8; ni++)
            #pragma unroll
            for (int q = 0; q < 4; q++) acc[mi][ni][q] = 0.f;

    uint32_t aRow = (uint32_t)(m0w + (lane & 7) + ((lane >> 3) & 1) * 8);
    uint32_t aK   = (uint32_t)((lane >> 4) * 8);
    uint32_t aBase = sb + SM_A + (aRow * LDA + aK) * 2;
    uint32_t bRow = (uint32_t)(n0w + (lane >> 4) * 8 + (lane & 7));
    uint32_t bK   = (uint32_t)(((lane >> 3) & 1) * 8);
    uint32_t bBase = sb + SM_B + (bRow * LDA + bK) * 2;

    #pragma unroll
    for (int ks = 0; ks < 8; ks++) {
        uint32_t k0b = ks * 16 * 2;
        uint32_t af[2][4];
        ldsm4(af[0], aBase + k0b);
        ldsm4(af[1], aBase + k0b + 16 * LDA * 2);
        uint32_t bf[8][2];
        #pragma unroll
        for (int np = 0; np < 4; np++) {
            uint32_t r4[4];
            ldsm4(r4, bBase + k0b + np * 16 * LDA * 2);
            bf[2 * np][0] = r4[0]; bf[2 * np][1] = r4[1];
            bf[2 * np + 1][0] = r4[2]; bf[2 * np + 1][1] = r4[3];
        }
        #pragma unroll
        for (int mi = 0; mi < 2; mi++)
            #pragma unroll
            for (int ni = 0; ni < 8; ni++)
                mma16816(acc[mi][ni], af[mi], bf[ni]);
    }
    __syncthreads();

    int g = lane >> 2, tig = lane & 3;
    #pragma unroll
    for (int mi = 0; mi < 2; mi++) {
        #pragma unroll
        for (int ni = 0; ni < 8; ni++) {
            int r = m0w + mi * 16 + g;
            int c = n0w + ni * 8 + tig * 2;
            float2 lo = make_float2(acc[mi][ni][0], acc[mi][ni][1]);
            float2 hi = make_float2(acc[mi][ni][2], acc[mi][ni][3]);
            *(float2*)&Cs[r * LDC + c] = lo;
            *(float2*)&Cs[(r + 8) * LDC + c] = hi;
        }
    }
    __syncthreads();

    int r = tid & 127, half = tid >> 7;
    int grow = row0 + r;
    if (grow < M) {
        int cl0 = half * 64;
        int hb = (col0 >> 5) + half * 2;
        float ps0 = 0.f, pd0 = 0.f, ps1 = 0.f, pd1 = 0.f;
        __half2 hh[32];
        #pragma unroll
        for (int j = 0; j < 16; j++) {
            float4 v = *(const float4*)&Cs[r * LDC + cl0 + j * 4];
            int gc = col0 + cl0 + j * 4;
            if (j < 8) {
                ps0 = fmaf(v.x, sas[gc], fmaf(v.y, sas[gc + 1],
                      fmaf(v.z, sas[gc + 2], fmaf(v.w, sas[gc + 3], ps0))));
                pd0 = fmaf(v.x, sad[gc], fmaf(v.y, sad[gc + 1],
                      fmaf(v.z, sad[gc + 2], fmaf(v.w, sad[gc + 3], pd0))));
            } else {
                ps1 = fmaf(v.x, sas[gc], fmaf(v.y, sas[gc + 1],
                      fmaf(v.z, sas[gc + 2], fmaf(v.w, sas[gc + 3], ps1))));
                pd1 = fmaf(v.x, sad[gc], fmaf(v.y, sad[gc + 1],
                      fmaf(v.z, sad[gc + 2], fmaf(v.w, sad[gc + 3], pd1))));
            }
            hh[j * 2] = __floats2half2_rn(v.x, v.y);
            hh[j * 2 + 1] = __floats2half2_rn(v.z, v.w);
        }
        g_asrc1[grow * 8 + hb] = ps0;
        g_adst1[grow * 8 + hb] = pd0;
        g_asrc1[grow * 8 + hb + 1] = ps1;
        g_adst1[grow * 8 + hb + 1] = pd1;
        uint4* dst = (uint4*)&g_h1h[(size_t)grow * 256 + col0 + cl0];
        #pragma unroll
        for (int q = 0; q < 8; q++) {
            uint4 pk;
            pk.x = *(unsigned*)&hh[q * 4 + 0];
            pk.y = *(unsigned*)&hh[q * 4 + 1];
            pk.z = *(unsigned*)&hh[q * 4 + 2];
            pk.w = *(unsigned*)&hh[q * 4 + 3];
            dst[q] = pk;
        }
    }
}

// ---------------- CSR build -------------------------------------------------
__global__ void k_hist(const void* __restrict__ ei, int E, int N) {
    int i = blockIdx.x * blockDim.x + threadIdx.x;
    if (i >= E + N) return;
    int d;
    if (i < E) {
        d = g_is64 ? (int)((const long long*)ei)[E + i]
                   : ((const int*)ei)[E + i];
    } else {
        d = i - E;
    }
    atomicAdd(&g_cnt[d], 1);
}

__global__ __launch_bounds__(256) void k_scan1(int N) {
    __shared__ int sd[256];
    int i = blockIdx.x * 256 + threadIdx.x;
    int v = (i < N) ? g_cnt[i] : 0;
    sd[threadIdx.x] = v;
    __syncthreads();
    #pragma unroll
    for (int s = 1; s < 256; s <<= 1) {
        int t = (threadIdx.x >= s) ? sd[threadIdx.x - s] : 0;
        __syncthreads();
        sd[threadIdx.x] += t;
        __syncthreads();
    }
    if (i < N) g_off[i] = sd[threadIdx.x] - v;
    if (threadIdx.x == 255) g_bsum[blockIdx.x] = sd[255];
}

__global__ __launch_bounds__(256) void k_scan2(int nb) {
    __shared__ int sd[256];
    int v = (threadIdx.x < nb) ? g_bsum[threadIdx.x] : 0;
    sd[threadIdx.x] = v;
    __syncthreads();
    #pragma unroll
    for (int s = 1; s < 256; s <<= 1) {
        int t = (threadIdx.x >= s) ? sd[threadIdx.x - s] : 0;
        __syncthreads();
        sd[threadIdx.x] += t;
        __syncthreads();
    }
    if (threadIdx.x < nb) g_bsum[threadIdx.x] = sd[threadIdx.x] - v;
}

__global__ __launch_bounds__(256) void k_scan3(int N, int total) {
    int i = blockIdx.x * 256 + threadIdx.x;
    if (i < N) {
        int o = g_off[i] + g_bsum[blockIdx.x];
        g_off[i] = o;
        g_cur[i] = o;
    }
    if (i == 0) g_off[N] = total;
}

__global__ void k_scatter(const void* __restrict__ ei, int E, int N) {
    int i = blockIdx.x * blockDim.x + threadIdx.x;
    if (i >= E + N) return;
    int s, d;
    if (i < E) {
        if (g_is64) {
            const long long* p = (const long long*)ei;
            s = (int)p[i]; d = (int)p[E + i];
        } else {
            const int* p = (const int*)ei;
            s = p[i]; d = p[E + i];
        }
    } else {
        s = d = i - E;
    }
    int pos = atomicAdd(&g_cur[d], 1);
    g_csr[pos] = s;
}

// ------- layer-1: SINGLE-PASS softmax agg + fused gemm2 + layer-2 logits ---
// alpha = exp(l)/sum(exp(l)); aggregate h*exp(l) and normalize at the end.
// No max pass (logits are O(1); exp cannot overflow fp32 here).
__global__ __launch_bounds__(256) void k_agg1(const float* __restrict__ bias1,
                                              const float* __restrict__ W2,
                                              const float* __restrict__ as2,
                                              const float* __restrict__ ad2,
                                              int N) {
    __shared__ float w2s[4096];     // W2 [256][16]
    __shared__ float sv[8][256];    // per-warp elu'd feature vector

    for (int i = threadIdx.x; i < 4096; i += 256) w2s[i] = W2[i];
    __syncthreads();

    int d = (blockIdx.x * blockDim.x + threadIdx.x) >> 5;
    int lane = threadIdx.x & 31;
    int wid = threadIdx.x >> 5;
    if (d >= N) return;
    int beg = g_off[d], end = g_off[d + 1];
    float adv = (lane < 8) ? g_adst1[d * 8 + lane] : 0.f;

    float2 acc[4];
    #pragma unroll
    for (int j = 0; j < 4; j++) acc[j] = make_float2(0.f, 0.f);
    int hj[4];
    #pragma unroll
    for (int j = 0; j < 4; j++) hj[j] = j * 2 + (lane >> 4);

    float sumw = 0.f;   // lanes 0-7: per-head sum of exp(l)
    const __half2* base = (const __half2*)g_h1h;
    for (int e = beg; e < end; e++) {
        int s = g_csr[e];
        float w = 0.f;
        if (lane < 8) {
            w = __expf(lrelu(g_asrc1[s * 8 + lane] + adv));
            sumw += w;
        }
        const __half2* hp = base + (size_t)s * 128 + lane;
        #pragma unroll
        for (int j = 0; j < 4; j++) {
            float wj = __shfl_sync(0xffffffffu, w, hj[j]);
            float2 f = __half22float2(hp[j * 32]);
            acc[j].x = fmaf(f.x, wj, acc[j].x);
            acc[j].y = fmaf(f.y, wj, acc[j].y);
        }
    }
    float inv = 1.f / (sumw + 1e-16f);   // valid on lanes 0-7

    // normalize + bias + ELU -> sv
    #pragma unroll
    for (int j = 0; j < 4; j++) {
        float invj = __shfl_sync(0xffffffffu, inv, hj[j]);
        int c = j * 64 + lane * 2;
        float2 bv = *(const float2*)&bias1[c];
        float vx = fmaf(acc[j].x, invj, bv.x);
        float vy = fmaf(acc[j].y, invj, bv.y);
        vx = vx > 0.f ? vx : expm1f(vx);
        vy = vy > 0.f ? vy : expm1f(vy);
        sv[wid][c] = vx;
        sv[wid][c + 1] = vy;
    }
    __syncwarp();

    // GEMV: h2 = sv @ W2 (256x16), conflict-free
    int n = lane & 15, half = lane >> 4;
    float yp = 0.f;
    #pragma unroll 8
    for (int t = 0; t < 128; t++) {
        int c = 2 * t + half;
        yp = fmaf(sv[wid][c], w2s[c * 16 + n], yp);
    }
    yp += __shfl_xor_sync(0xffffffffu, yp, 16);

    float ps = 0.f, pd = 0.f;
    if (lane < 16) {
        g_h2[d * 16 + lane] = yp;
        ps = yp * __ldg(&as2[lane]);
        pd = yp * __ldg(&ad2[lane]);
    }
    ps = warp_sum(ps);
    pd = warp_sum(pd);
    if (lane == 0) { g_asrc2[d] = ps; g_adst2[d] = pd; }
}

// ------- layer-2: SINGLE-PASS softmax agg (warp per dst) -------------------
__global__ __launch_bounds__(256) void k_agg2(const float* __restrict__ bias2,
                                              float* __restrict__ out, int N) {
    int d = (blockIdx.x * blockDim.x + threadIdx.x) >> 5;
    int lane = threadIdx.x & 31;
    if (d >= N) return;
    int beg = g_off[d], end = g_off[d + 1];
    float ad = g_adst2[d];

    float acc = 0.f, sumw = 0.f;
    for (int e = beg; e < end; e++) {
        int s = g_csr[e];
        float w = __expf(lrelu(g_asrc2[s] + ad));   // all lanes, broadcast load
        sumw += w;
        if (lane < 16) acc = fmaf(g_h2[s * 16 + lane], w, acc);
    }
    float inv = 1.f / (sumw + 1e-16f);
    if (lane < 16) out[d * 16 + lane] = fmaf(acc, inv, bias2[lane]);
}

// ---------------- launch ----------------------------------------------------
extern "C" void kernel_launch(void* const* d_in, const int* in_sizes, int n_in,
                              void* d_out, int out_size) {
    const float* x   = (const float*)d_in[0];
    const void*  ei  = d_in[1];
    const float* W1  = (const float*)d_in[2];
    const float* as1 = (const float*)d_in[3];
    const float* ad1 = (const float*)d_in[4];
    const float* b1  = (const float*)d_in[5];
    const float* W2  = (const float*)d_in[6];
    const float* as2 = (const float*)d_in[7];
    const float* ad2 = (const float*)d_in[8];
    const float* b2  = (const float*)d_in[9];
    float* out = (float*)d_out;

    int N = in_sizes[0] / 128;
    int E = in_sizes[1] / 2;
    int tot = E + N;
    int nb = (N + 255) / 256;

    k_init<<<196, 256>>>((const int*)ei, in_sizes[1], N, W1, x);

    cudaFuncSetAttribute(k_gemm1, cudaFuncAttributeMaxDynamicSharedMemorySize, SM_TOT);
    dim3 g1(2, (N + 127) / 128);
    k_gemm1<<<g1, 256, SM_TOT>>>(as1, ad1, N);

    k_hist<<<(tot + 255) / 256, 256>>>(ei, E, N);
    k_scan1<<<nb, 256>>>(N);
    k_scan2<<<1, 256>>>(nb);
    k_scan3<<<nb, 256>>>(N, tot);
    k_scatter<<<(tot + 255) / 256, 256>>>(ei, E, N);

    k_agg1<<<(N * 32 + 255) / 256, 256>>>(b1, W2, as2, ad2, N);
    k_agg2<<<(N * 32 + 255) / 256, 256>>>(b2, out, N);
}

// round 10
// speedup vs baseline: 2.3535x; 1.0369x over previous
#include <cuda_runtime.h>
#include <cuda_fp16.h>
#include <cstdint>

#define NMAX 50000
#define EMAX 800000
#define ETOTMAX (NMAX + EMAX)

// ---------------- scratch (device globals; no allocation allowed) ----------
__device__ __half g_h1h[NMAX * 256];   // layer-1 features (fp16, for gather)
__device__ __half g_xh[NMAX * 128];    // x converted to fp16
__device__ __half g_w1t[256 * 128];    // W1 transposed [n,k] fp16
__device__ float g_asrc1[NMAX * 8];
__device__ float g_adst1[NMAX * 8];
__device__ float g_h2[NMAX * 16];
__device__ float g_asrc2[NMAX];
__device__ float g_adst2[NMAX];
__device__ int   g_cnt[NMAX];
__device__ int   g_off[NMAX + 1];
__device__ int   g_cur[NMAX];
__device__ int   g_csr[ETOTMAX];
__device__ int   g_bsum[256];
__device__ int   g_is64;

__device__ __forceinline__ float lrelu(float x) { return x > 0.f ? x : 0.2f * x; }
__device__ __forceinline__ float warp_sum(float v) {
    #pragma unroll
    for (int o = 16; o; o >>= 1) v += __shfl_xor_sync(0xffffffffu, v, o);
    return v;
}

__device__ __forceinline__ uint32_t smem_u32(const void* p) {
    uint32_t a;
    asm("{ .reg .u64 t; cvta.to.shared.u64 t, %1; cvt.u32.u64 %0, t; }"
        : "=r"(a) : "l"(p));
    return a;
}

// ------- init: zero counters + dtype detect + W1->fp16^T + x->fp16 ---------
__global__ void k_init(const int* __restrict__ ei32, int twoE, int N,
                       const float* __restrict__ W1,
                       const float* __restrict__ x) {
    int i = blockIdx.x * blockDim.x + threadIdx.x;
    int nt = gridDim.x * blockDim.x;
    if (i < N) g_cnt[i] = 0;
    if (i < 256 * 128) {
        int n = i >> 7, k = i & 127;
        g_w1t[i] = __float2half(W1[k * 256 + n]);
    }
    int quads = N * 32;
    for (int q = i; q < quads; q += nt) {
        float4 f = *(const float4*)&x[(size_t)q * 4];
        __half2 h0 = __floats2half2_rn(f.x, f.y);
        __half2 h1 = __floats2half2_rn(f.z, f.w);
        uint2 pk;
        pk.x = *(unsigned*)&h0; pk.y = *(unsigned*)&h1;
        *(uint2*)&g_xh[(size_t)q * 4] = pk;
    }
    if (blockIdx.x == 0) {
        __shared__ int s_any;
        if (threadIdx.x == 0) s_any = 0;
        __syncthreads();
        int n = twoE < 2048 ? twoE : 2048;
        int nz = 0;
        for (int j = 2 * (int)threadIdx.x + 1; j < n; j += 2048)
            nz |= (ei32[j] != 0);
        if (nz) atomicOr(&s_any, 1);
        __syncthreads();
        if (threadIdx.x == 0) g_is64 = s_any ? 0 : 1;
    }
}

// ---------------- GEMM1 via mma.sync (HMMA) + fused att logits -------------
#define LDA 136
#define LDC 132
#define SM_A   0
#define SM_B   (128 * LDA * 2)
#define SM_ATT (2 * 128 * LDA * 2)
#define SM_TOT (SM_ATT + 2048)

__device__ __forceinline__ void ldsm4(uint32_t* r, uint32_t addr) {
    asm volatile("ldmatrix.sync.aligned.m8n8.x4.shared.b16 {%0,%1,%2,%3}, [%4];"
                 : "=r"(r[0]), "=r"(r[1]), "=r"(r[2]), "=r"(r[3]) : "r"(addr));
}
__device__ __forceinline__ void mma16816(float* c, const uint32_t* a, const uint32_t* b) {
    asm volatile(
        "mma.sync.aligned.m16n8k16.row.col.f32.f16.f16.f32 "
        "{%0,%1,%2,%3}, {%4,%5,%6,%7}, {%8,%9}, {%0,%1,%2,%3};"
        : "+f"(c[0]), "+f"(c[1]), "+f"(c[2]), "+f"(c[3])
        : "r"(a[0]), "r"(a[1]), "r"(a[2]), "r"(a[3]), "r"(b[0]), "r"(b[1]));
}

__global__ __launch_bounds__(256) void k_gemm1(const float* __restrict__ att_s,
                                               const float* __restrict__ att_d,
                                               int M) {
    extern __shared__ char smem[];
    uint32_t sb = smem_u32(smem);
    __half* As = (__half*)(smem + SM_A);
    __half* Bs = (__half*)(smem + SM_B);
    float* Cs = (float*)(smem + SM_A);
    float* sas = (float*)(smem + SM_ATT);
    float* sad = (float*)(smem + SM_ATT + 1024);

    int tid = threadIdx.x;
    int wid = tid >> 5, lane = tid & 31;
    int row0 = blockIdx.y * 128, col0 = blockIdx.x * 128;

    for (int i = tid; i < 256; i += 256) {
        sas[i] = att_s[i];
        sad[i] = att_d[i];
    }

    for (int i = tid; i < 128 * 16; i += 256) {
        int r = i >> 4, c8 = (i & 15) * 8;
        int gr = row0 + r;
        uint4 pk = make_uint4(0u, 0u, 0u, 0u);
        if (gr < M) pk = *(const uint4*)&g_xh[(size_t)gr * 128 + c8];
        *(uint4*)&As[r * LDA + c8] = pk;
    }
    for (int i = tid; i < 128 * 16; i += 256) {
        int n = i >> 4, c8 = (i & 15) * 8;
        uint4 pk = *(const uint4*)&g_w1t[(size_t)(col0 + n) * 128 + c8];
        *(uint4*)&Bs[n * LDA + c8] = pk;
    }
    __syncthreads();

    int wm = wid & 3, wn = wid >> 2;
    int m0w = wm * 32, n0w = wn * 64;

    float acc[2][8][4];
    #pragma unroll
    for (int mi = 0; mi < 2; mi++)
        #pragma unroll
        for (int ni = 0; ni < 8; ni++)
            #pragma unroll
            for (int q = 0; q < 4; q++) acc[mi][ni][q] = 0.f;

    uint32_t aRow = (uint32_t)(m0w + (lane & 7) + ((lane >> 3) & 1) * 8);
    uint32_t aK   = (uint32_t)((lane >> 4) * 8);
    uint32_t aBase = sb + SM_A + (aRow * LDA + aK) * 2;
    uint32_t bRow = (uint32_t)(n0w + (lane >> 4) * 8 + (lane & 7));
    uint32_t bK   = (uint32_t)(((lane >> 3) & 1) * 8);
    uint32_t bBase = sb + SM_B + (bRow * LDA + bK) * 2;

    #pragma unroll
    for (int ks = 0; ks < 8; ks++) {
        uint32_t k0b = ks * 16 * 2;
        uint32_t af[2][4];
        ldsm4(af[0], aBase + k0b);
        ldsm4(af[1], aBase + k0b + 16 * LDA * 2);
        uint32_t bf[8][2];
        #pragma unroll
        for (int np = 0; np < 4; np++) {
            uint32_t r4[4];
            ldsm4(r4, bBase + k0b + np * 16 * LDA * 2);
            bf[2 * np][0] = r4[0]; bf[2 * np][1] = r4[1];
            bf[2 * np + 1][0] = r4[2]; bf[2 * np + 1][1] = r4[3];
        }
        #pragma unroll
        for (int mi = 0; mi < 2; mi++)
            #pragma unroll
            for (int ni = 0; ni < 8; ni++)
                mma16816(acc[mi][ni], af[mi], bf[ni]);
    }
    __syncthreads();

    int g = lane >> 2, tig = lane & 3;
    #pragma unroll
    for (int mi = 0; mi < 2; mi++) {
        #pragma unroll
        for (int ni = 0; ni < 8; ni++) {
            int r = m0w + mi * 16 + g;
            int c = n0w + ni * 8 + tig * 2;
            float2 lo = make_float2(acc[mi][ni][0], acc[mi][ni][1]);
            float2 hi = make_float2(acc[mi][ni][2], acc[mi][ni][3]);
            *(float2*)&Cs[r * LDC + c] = lo;
            *(float2*)&Cs[(r + 8) * LDC + c] = hi;
        }
    }
    __syncthreads();

    int r = tid & 127, half = tid >> 7;
    int grow = row0 + r;
    if (grow < M) {
        int cl0 = half * 64;
        int hb = (col0 >> 5) + half * 2;
        float ps0 = 0.f, pd0 = 0.f, ps1 = 0.f, pd1 = 0.f;
        __half2 hh[32];
        #pragma unroll
        for (int j = 0; j < 16; j++) {
            float4 v = *(const float4*)&Cs[r * LDC + cl0 + j * 4];
            int gc = col0 + cl0 + j * 4;
            if (j < 8) {
                ps0 = fmaf(v.x, sas[gc], fmaf(v.y, sas[gc + 1],
                      fmaf(v.z, sas[gc + 2], fmaf(v.w, sas[gc + 3], ps0))));
                pd0 = fmaf(v.x, sad[gc], fmaf(v.y, sad[gc + 1],
                      fmaf(v.z, sad[gc + 2], fmaf(v.w, sad[gc + 3], pd0))));
            } else {
                ps1 = fmaf(v.x, sas[gc], fmaf(v.y, sas[gc + 1],
                      fmaf(v.z, sas[gc + 2], fmaf(v.w, sas[gc + 3], ps1))));
                pd1 = fmaf(v.x, sad[gc], fmaf(v.y, sad[gc + 1],
                      fmaf(v.z, sad[gc + 2], fmaf(v.w, sad[gc + 3], pd1))));
            }
            hh[j * 2] = __floats2half2_rn(v.x, v.y);
            hh[j * 2 + 1] = __floats2half2_rn(v.z, v.w);
        }
        g_asrc1[grow * 8 + hb] = ps0;
        g_adst1[grow * 8 + hb] = pd0;
        g_asrc1[grow * 8 + hb + 1] = ps1;
        g_adst1[grow * 8 + hb + 1] = pd1;
        uint4* dst = (uint4*)&g_h1h[(size_t)grow * 256 + col0 + cl0];
        #pragma unroll
        for (int q = 0; q < 8; q++) {
            uint4 pk;
            pk.x = *(unsigned*)&hh[q * 4 + 0];
            pk.y = *(unsigned*)&hh[q * 4 + 1];
            pk.z = *(unsigned*)&hh[q * 4 + 2];
            pk.w = *(unsigned*)&hh[q * 4 + 3];
            dst[q] = pk;
        }
    }
}

// ---------------- CSR build -------------------------------------------------
__global__ void k_hist(const void* __restrict__ ei, int E, int N) {
    int i = blockIdx.x * blockDim.x + threadIdx.x;
    if (i >= E + N) return;
    int d;
    if (i < E) {
        d = g_is64 ? (int)((const long long*)ei)[E + i]
                   : ((const int*)ei)[E + i];
    } else {
        d = i - E;
    }
    atomicAdd(&g_cnt[d], 1);
}

__global__ __launch_bounds__(256) void k_scan1(int N) {
    __shared__ int sd[256];
    int i = blockIdx.x * 256 + threadIdx.x;
    int v = (i < N) ? g_cnt[i] : 0;
    sd[threadIdx.x] = v;
    __syncthreads();
    #pragma unroll
    for (int s = 1; s < 256; s <<= 1) {
        int t = (threadIdx.x >= s) ? sd[threadIdx.x - s] : 0;
        __syncthreads();
        sd[threadIdx.x] += t;
        __syncthreads();
    }
    if (i < N) g_off[i] = sd[threadIdx.x] - v;
    if (threadIdx.x == 255) g_bsum[blockIdx.x] = sd[255];
}

__global__ __launch_bounds__(256) void k_scan2(int nb) {
    __shared__ int sd[256];
    int v = (threadIdx.x < nb) ? g_bsum[threadIdx.x] : 0;
    sd[threadIdx.x] = v;
    __syncthreads();
    #pragma unroll
    for (int s = 1; s < 256; s <<= 1) {
        int t = (threadIdx.x >= s) ? sd[threadIdx.x - s] : 0;
        __syncthreads();
        sd[threadIdx.x] += t;
        __syncthreads();
    }
    if (threadIdx.x < nb) g_bsum[threadIdx.x] = sd[threadIdx.x] - v;
}

__global__ __launch_bounds__(256) void k_scan3(int N, int total) {
    int i = blockIdx.x * 256 + threadIdx.x;
    if (i < N) {
        int o = g_off[i] + g_bsum[blockIdx.x];
        g_off[i] = o;
        g_cur[i] = o;
    }
    if (i == 0) g_off[N] = total;
}

__global__ void k_scatter(const void* __restrict__ ei, int E, int N) {
    int i = blockIdx.x * blockDim.x + threadIdx.x;
    if (i >= E + N) return;
    int s, d;
    if (i < E) {
        if (g_is64) {
            const long long* p = (const long long*)ei;
            s = (int)p[i]; d = (int)p[E + i];
        } else {
            const int* p = (const int*)ei;
            s = p[i]; d = p[E + i];
        }
    } else {
        s = d = i - E;
    }
    int pos = atomicAdd(&g_cur[d], 1);
    g_csr[pos] = s;
}

// ------- layer-1: single-pass softmax agg + fused gemm2 + layer-2 logits ---
__global__ __launch_bounds__(256) void k_agg1(const float* __restrict__ bias1,
                                              const float* __restrict__ W2,
                                              const float* __restrict__ as2,
                                              const float* __restrict__ ad2,
                                              int N) {
    __shared__ float w2s[4096];     // W2 [256][16]
    __shared__ float sv[8][256];    // per-warp elu'd feature vector

    for (int i = threadIdx.x; i < 4096; i += 256) w2s[i] = W2[i];
    __syncthreads();

    int d = (blockIdx.x * blockDim.x + threadIdx.x) >> 5;
    int lane = threadIdx.x & 31;
    int wid = threadIdx.x >> 5;
    if (d >= N) return;
    int beg = g_off[d], end = g_off[d + 1];
    float adv = (lane < 8) ? g_adst1[d * 8 + lane] : 0.f;

    float2 acc[4];
    #pragma unroll
    for (int j = 0; j < 4; j++) acc[j] = make_float2(0.f, 0.f);
    int hj[4];
    #pragma unroll
    for (int j = 0; j < 4; j++) hj[j] = j * 2 + (lane >> 4);

    float sumw = 0.f;   // lanes 0-7: per-head sum of exp(l)
    const __half2* base = (const __half2*)g_h1h;

    int e = beg;
    for (; e + 1 < end; e += 2) {           // 2 edges/iter for MLP
        int s0 = g_csr[e], s1 = g_csr[e + 1];
        float w0 = 0.f, w1 = 0.f;
        if (lane < 8) {
            w0 = __expf(lrelu(g_asrc1[s0 * 8 + lane] + adv));
            w1 = __expf(lrelu(g_asrc1[s1 * 8 + lane] + adv));
            sumw += w0 + w1;
        }
        const __half2* hp0 = base + (size_t)s0 * 128 + lane;
        const __half2* hp1 = base + (size_t)s1 * 128 + lane;
        #pragma unroll
        for (int j = 0; j < 4; j++) {
            float wj0 = __shfl_sync(0xffffffffu, w0, hj[j]);
            float wj1 = __shfl_sync(0xffffffffu, w1, hj[j]);
            float2 f0 = __half22float2(hp0[j * 32]);
            float2 f1 = __half22float2(hp1[j * 32]);
            acc[j].x = fmaf(f0.x, wj0, fmaf(f1.x, wj1, acc[j].x));
            acc[j].y = fmaf(f0.y, wj0, fmaf(f1.y, wj1, acc[j].y));
        }
    }
    if (e < end) {
        int s0 = g_csr[e];
        float w0 = 0.f;
        if (lane < 8) {
            w0 = __expf(lrelu(g_asrc1[s0 * 8 + lane] + adv));
            sumw += w0;
        }
        const __half2* hp0 = base + (size_t)s0 * 128 + lane;
        #pragma unroll
        for (int j = 0; j < 4; j++) {
            float wj0 = __shfl_sync(0xffffffffu, w0, hj[j]);
            float2 f0 = __half22float2(hp0[j * 32]);
            acc[j].x = fmaf(f0.x, wj0, acc[j].x);
            acc[j].y = fmaf(f0.y, wj0, acc[j].y);
        }
    }
    float inv = 1.f / (sumw + 1e-16f);   // valid on lanes 0-7

    // normalize + bias + ELU -> sv
    #pragma unroll
    for (int j = 0; j < 4; j++) {
        float invj = __shfl_sync(0xffffffffu, inv, hj[j]);
        int c = j * 64 + lane * 2;
        float2 bv = *(const float2*)&bias1[c];
        float vx = fmaf(acc[j].x, invj, bv.x);
        float vy = fmaf(acc[j].y, invj, bv.y);
        vx = vx > 0.f ? vx : expm1f(vx);
        vy = vy > 0.f ? vy : expm1f(vy);
        sv[wid][c] = vx;
        sv[wid][c + 1] = vy;
    }
    __syncwarp();

    // GEMV: h2 = sv @ W2 (256x16), conflict-free
    int n = lane & 15, half = lane >> 4;
    float yp = 0.f;
    #pragma unroll 8
    for (int t = 0; t < 128; t++) {
        int c = 2 * t + half;
        yp = fmaf(sv[wid][c], w2s[c * 16 + n], yp);
    }
    yp += __shfl_xor_sync(0xffffffffu, yp, 16);

    float ps = 0.f, pd = 0.f;
    if (lane < 16) {
        g_h2[d * 16 + lane] = yp;
        ps = yp * __ldg(&as2[lane]);
        pd = yp * __ldg(&ad2[lane]);
    }
    ps = warp_sum(ps);
    pd = warp_sum(pd);
    if (lane == 0) { g_asrc2[d] = ps; g_adst2[d] = pd; }
}

// ------- layer-2: single-pass softmax agg (warp per dst) -------------------
__global__ __launch_bounds__(256) void k_agg2(const float* __restrict__ bias2,
                                              float* __restrict__ out, int N) {
    int d = (blockIdx.x * blockDim.x + threadIdx.x) >> 5;
    int lane = threadIdx.x & 31;
    if (d >= N) return;
    int beg = g_off[d], end = g_off[d + 1];
    float ad = g_adst2[d];

    float acc = 0.f, sumw = 0.f;
    int e = beg;
    for (; e + 1 < end; e += 2) {
        int s0 = g_csr[e], s1 = g_csr[e + 1];
        float w0 = __expf(lrelu(g_asrc2[s0] + ad));
        float w1 = __expf(lrelu(g_asrc2[s1] + ad));
        sumw += w0 + w1;
        if (lane < 16)
            acc = fmaf(g_h2[s0 * 16 + lane], w0,
                  fmaf(g_h2[s1 * 16 + lane], w1, acc));
    }
    if (e < end) {
        int s0 = g_csr[e];
        float w0 = __expf(lrelu(g_asrc2[s0] + ad));
        sumw += w0;
        if (lane < 16) acc = fmaf(g_h2[s0 * 16 + lane], w0, acc);
    }
    float inv = 1.f / (sumw + 1e-16f);
    if (lane < 16) out[d * 16 + lane] = fmaf(acc, inv, bias2[lane]);
}

// ---------------- launch ----------------------------------------------------
extern "C" void kernel_launch(void* const* d_in, const int* in_sizes, int n_in,
                              void* d_out, int out_size) {
    const float* x   = (const float*)d_in[0];
    const void*  ei  = d_in[1];
    const float* W1  = (const float*)d_in[2];
    const float* as1 = (const float*)d_in[3];
    const float* ad1 = (const float*)d_in[4];
    const float* b1  = (const float*)d_in[5];
    const float* W2  = (const float*)d_in[6];
    const float* as2 = (const float*)d_in[7];
    const float* ad2 = (const float*)d_in[8];
    const float* b2  = (const float*)d_in[9];
    float* out = (float*)d_out;

    int N = in_sizes[0] / 128;
    int E = in_sizes[1] / 2;
    int tot = E + N;
    int nb = (N + 255) / 256;

    // side stream + events (created once, pre-capture on first call)
    static cudaStream_t s2 = nullptr;
    static cudaEvent_t evA = nullptr, evB = nullptr;
    if (!s2) {
        cudaStreamCreateWithFlags(&s2, cudaStreamNonBlocking);
        cudaEventCreateWithFlags(&evA, cudaEventDisableTiming);
        cudaEventCreateWithFlags(&evB, cudaEventDisableTiming);
        cudaFuncSetAttribute(k_gemm1, cudaFuncAttributeMaxDynamicSharedMemorySize, SM_TOT);
    }

    k_init<<<196, 256>>>((const int*)ei, in_sizes[1], N, W1, x);

    // fork: gemm1 on s2, CSR chain on stream 0; both depend on k_init
    cudaEventRecord(evA, 0);
    cudaStreamWaitEvent(s2, evA, 0);

    dim3 g1(2, (N + 127) / 128);
    k_gemm1<<<g1, 256, SM_TOT, s2>>>(as1, ad1, N);
    cudaEventRecord(evB, s2);

    k_hist<<<(tot + 255) / 256, 256>>>(ei, E, N);
    k_scan1<<<nb, 256>>>(N);
    k_scan2<<<1, 256>>>(nb);
    k_scan3<<<nb, 256>>>(N, tot);
    k_scatter<<<(tot + 255) / 256, 256>>>(ei, E, N);

    // join: agg1 needs gemm1 results
    cudaStreamWaitEvent(0, evB, 0);

    k_agg1<<<(N * 32 + 255) / 256, 256>>>(b1, W2, as2, ad2, N);
    k_agg2<<<(N * 32 + 255) / 256, 256>>>(b2, out, N);
}

// round 11
// speedup vs baseline: 2.5843x; 1.0980x over previous
#include <cuda_runtime.h>
#include <cuda_fp16.h>
#include <cstdint>

#define NMAX 50000
#define EMAX 800000
#define ETOTMAX (NMAX + EMAX)

// ---------------- scratch (device globals; no allocation allowed) ----------
__device__ __half g_h1h[NMAX * 256];   // layer-1 features (fp16, for gather)
__device__ __half g_xh[NMAX * 128];    // x converted to fp16
__device__ __half g_w1t[256 * 128];    // W1 transposed [n,k] fp16
__device__ float g_asrc1[NMAX * 8];
__device__ float g_adst1[NMAX * 8];
__device__ float g_h2[NMAX * 16];
__device__ float g_asrc2[NMAX];
__device__ float g_adst2[NMAX];
__device__ int   g_cnt[NMAX];
__device__ int   g_off[NMAX + 1];
__device__ int   g_cur[NMAX];
__device__ int   g_csr[ETOTMAX];
__device__ int   g_bsum[256];
__device__ int   g_is64;

__device__ __forceinline__ float lrelu(float x) { return x > 0.f ? x : 0.2f * x; }
__device__ __forceinline__ float warp_sum(float v) {
    #pragma unroll
    for (int o = 16; o; o >>= 1) v += __shfl_xor_sync(0xffffffffu, v, o);
    return v;
}

__device__ __forceinline__ uint32_t smem_u32(const void* p) {
    uint32_t a;
    asm("{ .reg .u64 t; cvta.to.shared.u64 t, %1; cvt.u32.u64 %0, t; }"
        : "=r"(a) : "l"(p));
    return a;
}

// ------- init: zero counters + dtype detect + W1->fp16^T + x->fp16 ---------
__global__ void k_init(const int* __restrict__ ei32, int twoE, int N,
                       const float* __restrict__ W1,
                       const float* __restrict__ x) {
    int i = blockIdx.x * blockDim.x + threadIdx.x;
    int nt = gridDim.x * blockDim.x;
    if (i < N) g_cnt[i] = 0;
    if (i < 256 * 128) {
        int n = i >> 7, k = i & 127;
        g_w1t[i] = __float2half(W1[k * 256 + n]);
    }
    int quads = N * 32;
    for (int q = i; q < quads; q += nt) {
        float4 f = *(const float4*)&x[(size_t)q * 4];
        __half2 h0 = __floats2half2_rn(f.x, f.y);
        __half2 h1 = __floats2half2_rn(f.z, f.w);
        uint2 pk;
        pk.x = *(unsigned*)&h0; pk.y = *(unsigned*)&h1;
        *(uint2*)&g_xh[(size_t)q * 4] = pk;
    }
    if (blockIdx.x == 0) {
        __shared__ int s_any;
        if (threadIdx.x == 0) s_any = 0;
        __syncthreads();
        int n = twoE < 2048 ? twoE : 2048;
        int nz = 0;
        for (int j = 2 * (int)threadIdx.x + 1; j < n; j += 2048)
            nz |= (ei32[j] != 0);
        if (nz) atomicOr(&s_any, 1);
        __syncthreads();
        if (threadIdx.x == 0) g_is64 = s_any ? 0 : 1;
    }
}

// ---------------- GEMM1 via mma.sync (HMMA) + fused att logits -------------
#define LDA 136
#define LDC 132
#define SM_A   0
#define SM_B   (128 * LDA * 2)
#define SM_ATT (2 * 128 * LDA * 2)
#define SM_TOT (SM_ATT + 2048)

__device__ __forceinline__ void ldsm4(uint32_t* r, uint32_t addr) {
    asm volatile("ldmatrix.sync.aligned.m8n8.x4.shared.b16 {%0,%1,%2,%3}, [%4];"
                 : "=r"(r[0]), "=r"(r[1]), "=r"(r[2]), "=r"(r[3]) : "r"(addr));
}
__device__ __forceinline__ void mma16816(float* c, const uint32_t* a, const uint32_t* b) {
    asm volatile(
        "mma.sync.aligned.m16n8k16.row.col.f32.f16.f16.f32 "
        "{%0,%1,%2,%3}, {%4,%5,%6,%7}, {%8,%9}, {%0,%1,%2,%3};"
        : "+f"(c[0]), "+f"(c[1]), "+f"(c[2]), "+f"(c[3])
        : "r"(a[0]), "r"(a[1]), "r"(a[2]), "r"(a[3]), "r"(b[0]), "r"(b[1]));
}

__global__ __launch_bounds__(256) void k_gemm1(const float* __restrict__ att_s,
                                               const float* __restrict__ att_d,
                                               int M) {
    extern __shared__ char smem[];
    uint32_t sb = smem_u32(smem);
    __half* As = (__half*)(smem + SM_A);
    __half* Bs = (__half*)(smem + SM_B);
    float* Cs = (float*)(smem + SM_A);
    float* sas = (float*)(smem + SM_ATT);
    float* sad = (float*)(smem + SM_ATT + 1024);

    int tid = threadIdx.x;
    int wid = tid >> 5, lane = tid & 31;
    int row0 = blockIdx.y * 128, col0 = blockIdx.x * 128;

    for (int i = tid; i < 256; i += 256) {
        sas[i] = att_s[i];
        sad[i] = att_d[i];
    }

    for (int i = tid; i < 128 * 16; i += 256) {
        int r = i >> 4, c8 = (i & 15) * 8;
        int gr = row0 + r;
        uint4 pk = make_uint4(0u, 0u, 0u, 0u);
        if (gr < M) pk = *(const uint4*)&g_xh[(size_t)gr * 128 + c8];
        *(uint4*)&As[r * LDA + c8] = pk;
    }
    for (int i = tid; i < 128 * 16; i += 256) {
        int n = i >> 4, c8 = (i & 15) * 8;
        uint4 pk = *(const uint4*)&g_w1t[(size_t)(col0 + n) * 128 + c8];
        *(uint4*)&Bs[n * LDA + c8] = pk;
    }
    __syncthreads();

    int wm = wid & 3, wn = wid >> 2;
    int m0w = wm * 32, n0w = wn * 64;

    float acc[2][8][4];
    #pragma unroll
    for (int mi = 0; mi < 2; mi++)
        #pragma unroll
        for (int ni = 0; ni < 8; ni++)
            #pragma unroll
            for (int q = 0; q < 4; q++) acc[mi][ni][q] = 0.f;

    uint32_t aRow = (uint32_t)(m0w + (lane & 7) + ((lane >> 3) & 1) * 8);
    uint32_t aK   = (uint32_t)((lane >> 4) * 8);
    uint32_t aBase = sb + SM_A + (aRow * LDA + aK) * 2;
    uint32_t bRow = (uint32_t)(n0w + (lane >> 4) * 8 + (lane & 7));
    uint32_t bK   = (uint32_t)(((lane >> 3) & 1) * 8);
    uint32_t bBase = sb + SM_B + (bRow * LDA + bK) * 2;

    #pragma unroll
    for (int ks = 0; ks < 8; ks++) {
        uint32_t k0b = ks * 16 * 2;
        uint32_t af[2][4];
        ldsm4(af[0], aBase + k0b);
        ldsm4(af[1], aBase + k0b + 16 * LDA * 2);
        uint32_t bf[8][2];
        #pragma unroll
        for (int np = 0; np < 4; np++) {
            uint32_t r4[4];
            ldsm4(r4, bBase + k0b + np * 16 * LDA * 2);
            bf[2 * np][0] = r4[0]; bf[2 * np][1] = r4[1];
            bf[2 * np + 1][0] = r4[2]; bf[2 * np + 1][1] = r4[3];
        }
        #pragma unroll
        for (int mi = 0; mi < 2; mi++)
            #pragma unroll
            for (int ni = 0; ni < 8; ni++)
                mma16816(acc[mi][ni], af[mi], bf[ni]);
    }
    __syncthreads();

    int g = lane >> 2, tig = lane & 3;
    #pragma unroll
    for (int mi = 0; mi < 2; mi++) {
        #pragma unroll
        for (int ni = 0; ni < 8; ni++) {
            int r = m0w + mi * 16 + g;
            int c = n0w + ni * 8 + tig * 2;
            float2 lo = make_float2(acc[mi][ni][0], acc[mi][ni][1]);
            float2 hi = make_float2(acc[mi][ni][2], acc[mi][ni][3]);
            *(float2*)&Cs[r * LDC + c] = lo;
            *(float2*)&Cs[(r + 8) * LDC + c] = hi;
        }
    }
    __syncthreads();

    int r = tid & 127, half = tid >> 7;
    int grow = row0 + r;
    if (grow < M) {
        int cl0 = half * 64;
        int hb = (col0 >> 5) + half * 2;
        float ps0 = 0.f, pd0 = 0.f, ps1 = 0.f, pd1 = 0.f;
        __half2 hh[32];
        #pragma unroll
        for (int j = 0; j < 16; j++) {
            float4 v = *(const float4*)&Cs[r * LDC + cl0 + j * 4];
            int gc = col0 + cl0 + j * 4;
            if (j < 8) {
                ps0 = fmaf(v.x, sas[gc], fmaf(v.y, sas[gc + 1],
                      fmaf(v.z, sas[gc + 2], fmaf(v.w, sas[gc + 3], ps0))));
                pd0 = fmaf(v.x, sad[gc], fmaf(v.y, sad[gc + 1],
                      fmaf(v.z, sad[gc + 2], fmaf(v.w, sad[gc + 3], pd0))));
            } else {
                ps1 = fmaf(v.x, sas[gc], fmaf(v.y, sas[gc + 1],
                      fmaf(v.z, sas[gc + 2], fmaf(v.w, sas[gc + 3], ps1))));
                pd1 = fmaf(v.x, sad[gc], fmaf(v.y, sad[gc + 1],
                      fmaf(v.z, sad[gc + 2], fmaf(v.w, sad[gc + 3], pd1))));
            }
            hh[j * 2] = __floats2half2_rn(v.x, v.y);
            hh[j * 2 + 1] = __floats2half2_rn(v.z, v.w);
        }
        g_asrc1[grow * 8 + hb] = ps0;
        g_adst1[grow * 8 + hb] = pd0;
        g_asrc1[grow * 8 + hb + 1] = ps1;
        g_adst1[grow * 8 + hb + 1] = pd1;
        uint4* dst = (uint4*)&g_h1h[(size_t)grow * 256 + col0 + cl0];
        #pragma unroll
        for (int q = 0; q < 8; q++) {
            uint4 pk;
            pk.x = *(unsigned*)&hh[q * 4 + 0];
            pk.y = *(unsigned*)&hh[q * 4 + 1];
            pk.z = *(unsigned*)&hh[q * 4 + 2];
            pk.w = *(unsigned*)&hh[q * 4 + 3];
            dst[q] = pk;
        }
    }
}

// ---------------- CSR build -------------------------------------------------
__global__ void k_hist(const void* __restrict__ ei, int E, int N) {
    int i = blockIdx.x * blockDim.x + threadIdx.x;
    if (i >= E + N) return;
    int d;
    if (i < E) {
        d = g_is64 ? (int)((const long long*)ei)[E + i]
                   : ((const int*)ei)[E + i];
    } else {
        d = i - E;
    }
    atomicAdd(&g_cnt[d], 1);
}

__global__ __launch_bounds__(256) void k_scan1(int N) {
    __shared__ int sd[256];
    int i = blockIdx.x * 256 + threadIdx.x;
    int v = (i < N) ? g_cnt[i] : 0;
    sd[threadIdx.x] = v;
    __syncthreads();
    #pragma unroll
    for (int s = 1; s < 256; s <<= 1) {
        int t = (threadIdx.x >= s) ? sd[threadIdx.x - s] : 0;
        __syncthreads();
        sd[threadIdx.x] += t;
        __syncthreads();
    }
    if (i < N) g_off[i] = sd[threadIdx.x] - v;
    if (threadIdx.x == 255) g_bsum[blockIdx.x] = sd[255];
}

__global__ __launch_bounds__(256) void k_scan2(int nb) {
    __shared__ int sd[256];
    int v = (threadIdx.x < nb) ? g_bsum[threadIdx.x] : 0;
    sd[threadIdx.x] = v;
    __syncthreads();
    #pragma unroll
    for (int s = 1; s < 256; s <<= 1) {
        int t = (threadIdx.x >= s) ? sd[threadIdx.x - s] : 0;
        __syncthreads();
        sd[threadIdx.x] += t;
        __syncthreads();
    }
    if (threadIdx.x < nb) g_bsum[threadIdx.x] = sd[threadIdx.x] - v;
}

__global__ __launch_bounds__(256) void k_scan3(int N, int total) {
    int i = blockIdx.x * 256 + threadIdx.x;
    if (i < N) {
        int o = g_off[i] + g_bsum[blockIdx.x];
        g_off[i] = o;
        g_cur[i] = o;
    }
    if (i == 0) g_off[N] = total;
}

__global__ void k_scatter(const void* __restrict__ ei, int E, int N) {
    int i = blockIdx.x * blockDim.x + threadIdx.x;
    if (i >= E + N) return;
    int s, d;
    if (i < E) {
        if (g_is64) {
            const long long* p = (const long long*)ei;
            s = (int)p[i]; d = (int)p[E + i];
        } else {
            const int* p = (const int*)ei;
            s = p[i]; d = p[E + i];
        }
    } else {
        s = d = i - E;
    }
    int pos = atomicAdd(&g_cur[d], 1);
    g_csr[pos] = s;
}

// ------- layer-1: single-pass softmax agg (shfl-free) + fused gemm2 --------
// lane owns 8 contiguous cols [lane*8, lane*8+8) -> exactly one head (lane>>2).
// Every lane computes its own edge weight; sumw is per-lane (identical within head).
__device__ __forceinline__ void fma8(float* acc, uint4 pk, float w) {
    __half2 h0 = *(__half2*)&pk.x, h1 = *(__half2*)&pk.y;
    __half2 h2 = *(__half2*)&pk.z, h3 = *(__half2*)&pk.w;
    float2 f0 = __half22float2(h0), f1 = __half22float2(h1);
    float2 f2 = __half22float2(h2), f3 = __half22float2(h3);
    acc[0] = fmaf(f0.x, w, acc[0]); acc[1] = fmaf(f0.y, w, acc[1]);
    acc[2] = fmaf(f1.x, w, acc[2]); acc[3] = fmaf(f1.y, w, acc[3]);
    acc[4] = fmaf(f2.x, w, acc[4]); acc[5] = fmaf(f2.y, w, acc[5]);
    acc[6] = fmaf(f3.x, w, acc[6]); acc[7] = fmaf(f3.y, w, acc[7]);
}

__global__ __launch_bounds__(256) void k_agg1(const float* __restrict__ bias1,
                                              const float* __restrict__ W2,
                                              const float* __restrict__ as2,
                                              const float* __restrict__ ad2,
                                              int N) {
    __shared__ float w2s[4096];     // W2 [256][16]
    __shared__ float sv[8][256];    // per-warp elu'd feature vector

    for (int i = threadIdx.x; i < 4096; i += 256) w2s[i] = W2[i];
    __syncthreads();

    int d = (blockIdx.x * blockDim.x + threadIdx.x) >> 5;
    int lane = threadIdx.x & 31;
    int wid = threadIdx.x >> 5;
    if (d >= N) return;
    int beg = g_off[d], end = g_off[d + 1];
    int h = lane >> 2;                      // head of this lane's 8 cols
    float adv = g_adst1[d * 8 + h];

    float acc[8];
    #pragma unroll
    for (int q = 0; q < 8; q++) acc[q] = 0.f;
    float sumw = 0.f;

    const uint4* base = (const uint4*)g_h1h;   // row = 32 uint4
    int e = beg;
    for (; e + 1 < end; e += 2) {
        int s0 = g_csr[e], s1 = g_csr[e + 1];
        float w0 = __expf(lrelu(g_asrc1[s0 * 8 + h] + adv));
        float w1 = __expf(lrelu(g_asrc1[s1 * 8 + h] + adv));
        sumw += w0 + w1;
        uint4 p0 = base[(size_t)s0 * 32 + lane];
        uint4 p1 = base[(size_t)s1 * 32 + lane];
        fma8(acc, p0, w0);
        fma8(acc, p1, w1);
    }
    if (e < end) {
        int s0 = g_csr[e];
        float w0 = __expf(lrelu(g_asrc1[s0 * 8 + h] + adv));
        sumw += w0;
        uint4 p0 = base[(size_t)s0 * 32 + lane];
        fma8(acc, p0, w0);
    }
    float inv = 1.f / (sumw + 1e-16f);

    // normalize + bias + ELU -> sv (cols lane*8 .. lane*8+7)
    const float* bp = bias1 + lane * 8;
    float* svp = &sv[wid][lane * 8];
    #pragma unroll
    for (int q = 0; q < 8; q++) {
        float v = fmaf(acc[q], inv, bp[q]);
        svp[q] = v > 0.f ? v : expm1f(v);
    }
    __syncwarp();

    // GEMV: h2 = sv @ W2 (256x16), conflict-free
    int n = lane & 15, half = lane >> 4;
    float yp = 0.f;
    #pragma unroll 8
    for (int t = 0; t < 128; t++) {
        int c = 2 * t + half;
        yp = fmaf(sv[wid][c], w2s[c * 16 + n], yp);
    }
    yp += __shfl_xor_sync(0xffffffffu, yp, 16);

    float ps = 0.f, pd = 0.f;
    if (lane < 16) {
        g_h2[d * 16 + lane] = yp;
        ps = yp * __ldg(&as2[lane]);
        pd = yp * __ldg(&ad2[lane]);
    }
    ps = warp_sum(ps);
    pd = warp_sum(pd);
    if (lane == 0) { g_asrc2[d] = ps; g_adst2[d] = pd; }
}

// ------- layer-2: single-pass softmax agg (half-warp per dst) --------------
__global__ __launch_bounds__(256) void k_agg2(const float* __restrict__ bias2,
                                              float* __restrict__ out, int N) {
    int lane = threadIdx.x & 31;
    int half = lane >> 4, l16 = lane & 15;
    int d = ((blockIdx.x * blockDim.x + threadIdx.x) >> 5) * 2 + half;
    if (d >= N) return;
    int beg = g_off[d], end = g_off[d + 1];
    float ad = g_adst2[d];

    float acc = 0.f, sumw = 0.f;
    int e = beg;
    for (; e + 1 < end; e += 2) {
        int s0 = g_csr[e], s1 = g_csr[e + 1];
        float w0 = __expf(lrelu(g_asrc2[s0] + ad));
        float w1 = __expf(lrelu(g_asrc2[s1] + ad));
        sumw += w0 + w1;
        acc = fmaf(g_h2[s0 * 16 + l16], w0,
              fmaf(g_h2[s1 * 16 + l16], w1, acc));
    }
    if (e < end) {
        int s0 = g_csr[e];
        float w0 = __expf(lrelu(g_asrc2[s0] + ad));
        sumw += w0;
        acc = fmaf(g_h2[s0 * 16 + l16], w0, acc);
    }
    float inv = 1.f / (sumw + 1e-16f);
    out[d * 16 + l16] = fmaf(acc, inv, bias2[l16]);
}

// ---------------- launch ----------------------------------------------------
extern "C" void kernel_launch(void* const* d_in, const int* in_sizes, int n_in,
                              void* d_out, int out_size) {
    const float* x   = (const float*)d_in[0];
    const void*  ei  = d_in[1];
    const float* W1  = (const float*)d_in[2];
    const float* as1 = (const float*)d_in[3];
    const float* ad1 = (const float*)d_in[4];
    const float* b1  = (const float*)d_in[5];
    const float* W2  = (const float*)d_in[6];
    const float* as2 = (const float*)d_in[7];
    const float* ad2 = (const float*)d_in[8];
    const float* b2  = (const float*)d_in[9];
    float* out = (float*)d_out;

    int N = in_sizes[0] / 128;
    int E = in_sizes[1] / 2;
    int tot = E + N;
    int nb = (N + 255) / 256;

    static cudaStream_t s2 = nullptr;
    static cudaEvent_t evA = nullptr, evB = nullptr;
    if (!s2) {
        cudaStreamCreateWithFlags(&s2, cudaStreamNonBlocking);
        cudaEventCreateWithFlags(&evA, cudaEventDisableTiming);
        cudaEventCreateWithFlags(&evB, cudaEventDisableTiming);
        cudaFuncSetAttribute(k_gemm1, cudaFuncAttributeMaxDynamicSharedMemorySize, SM_TOT);
    }

    k_init<<<196, 256>>>((const int*)ei, in_sizes[1], N, W1, x);

    cudaEventRecord(evA, 0);
    cudaStreamWaitEvent(s2, evA, 0);

    dim3 g1(2, (N + 127) / 128);
    k_gemm1<<<g1, 256, SM_TOT, s2>>>(as1, ad1, N);
    cudaEventRecord(evB, s2);

    k_hist<<<(tot + 255) / 256, 256>>>(ei, E, N);
    k_scan1<<<nb, 256>>>(N);
    k_scan2<<<1, 256>>>(nb);
    k_scan3<<<nb, 256>>>(N, tot);
    k_scatter<<<(tot + 255) / 256, 256>>>(ei, E, N);

    cudaStreamWaitEvent(0, evB, 0);

    k_agg1<<<(N * 32 + 255) / 256, 256>>>(b1, W2, as2, ad2, N);
    k_agg2<<<(N * 16 + 255) / 256, 256>>>(b2, out, N);
}

// round 12
// speedup vs baseline: 2.6161x; 1.0123x over previous
#include <cuda_runtime.h>
#include <cuda_fp16.h>
#include <cstdint>

#define NMAX 50000
#define EMAX 800000
#define ETOTMAX (NMAX + EMAX)

// ---------------- scratch (device globals; no allocation allowed) ----------
__device__ __half g_h1h[NMAX * 256];   // layer-1 features (fp16, for gather)
__device__ __half g_xh[NMAX * 128];    // x converted to fp16
__device__ __half g_w1t[256 * 128];    // W1 transposed [n,k] fp16
__device__ float g_asrc1[NMAX * 8];
__device__ float g_adst1[NMAX * 8];
__device__ float g_h2[NMAX * 16];
__device__ float g_asrc2[NMAX];
__device__ float g_adst2[NMAX];
__device__ int   g_cnt[NMAX];
__device__ int   g_off[NMAX + 1];
__device__ int   g_cur[NMAX];
__device__ int   g_csr[ETOTMAX];
__device__ int   g_bsum[256];
__device__ int   g_is64;

__device__ __forceinline__ float lrelu(float x) { return x > 0.f ? x : 0.2f * x; }
__device__ __forceinline__ float warp_sum(float v) {
    #pragma unroll
    for (int o = 16; o; o >>= 1) v += __shfl_xor_sync(0xffffffffu, v, o);
    return v;
}

__device__ __forceinline__ uint32_t smem_u32(const void* p) {
    uint32_t a;
    asm("{ .reg .u64 t; cvta.to.shared.u64 t, %1; cvt.u32.u64 %0, t; }"
        : "=r"(a) : "l"(p));
    return a;
}

// ------- init0: zero counters + dtype detect (CSR-chain leg) ----------------
__global__ void k_init0(const int* __restrict__ ei32, int twoE, int N) {
    int i = blockIdx.x * blockDim.x + threadIdx.x;
    if (i < N) g_cnt[i] = 0;
    if (blockIdx.x == 0) {
        __shared__ int s_any;
        if (threadIdx.x == 0) s_any = 0;
        __syncthreads();
        int n = twoE < 2048 ? twoE : 2048;
        int nz = 0;
        for (int j = 2 * (int)threadIdx.x + 1; j < n; j += 1024)
            nz |= (ei32[j] != 0);
        if (nz) atomicOr(&s_any, 1);
        __syncthreads();
        if (threadIdx.x == 0) g_is64 = s_any ? 0 : 1;
    }
}

// ------- initx: W1->fp16^T + x->fp16 (gemm leg, side stream) ---------------
__global__ void k_initx(int N, const float* __restrict__ W1,
                        const float* __restrict__ x) {
    int i = blockIdx.x * blockDim.x + threadIdx.x;
    int nt = gridDim.x * blockDim.x;
    if (i < 256 * 128) {
        int n = i >> 7, k = i & 127;
        g_w1t[i] = __float2half(W1[k * 256 + n]);
    }
    int quads = N * 32;
    for (int q = i; q < quads; q += nt) {
        float4 f = *(const float4*)&x[(size_t)q * 4];
        __half2 h0 = __floats2half2_rn(f.x, f.y);
        __half2 h1 = __floats2half2_rn(f.z, f.w);
        uint2 pk;
        pk.x = *(unsigned*)&h0; pk.y = *(unsigned*)&h1;
        *(uint2*)&g_xh[(size_t)q * 4] = pk;
    }
}

// ---------------- GEMM1 via mma.sync (HMMA) + fused att logits -------------
#define LDA 136
#define LDC 132
#define SM_A   0
#define SM_B   (128 * LDA * 2)
#define SM_ATT (2 * 128 * LDA * 2)
#define SM_TOT (SM_ATT + 2048)

__device__ __forceinline__ void ldsm4(uint32_t* r, uint32_t addr) {
    asm volatile("ldmatrix.sync.aligned.m8n8.x4.shared.b16 {%0,%1,%2,%3}, [%4];"
                 : "=r"(r[0]), "=r"(r[1]), "=r"(r[2]), "=r"(r[3]) : "r"(addr));
}
__device__ __forceinline__ void mma16816(float* c, const uint32_t* a, const uint32_t* b) {
    asm volatile(
        "mma.sync.aligned.m16n8k16.row.col.f32.f16.f16.f32 "
        "{%0,%1,%2,%3}, {%4,%5,%6,%7}, {%8,%9}, {%0,%1,%2,%3};"
        : "+f"(c[0]), "+f"(c[1]), "+f"(c[2]), "+f"(c[3])
        : "r"(a[0]), "r"(a[1]), "r"(a[2]), "r"(a[3]), "r"(b[0]), "r"(b[1]));
}

__global__ __launch_bounds__(256) void k_gemm1(const float* __restrict__ att_s,
                                               const float* __restrict__ att_d,
                                               int M) {
    extern __shared__ char smem[];
    uint32_t sb = smem_u32(smem);
    __half* As = (__half*)(smem + SM_A);
    __half* Bs = (__half*)(smem + SM_B);
    float* Cs = (float*)(smem + SM_A);
    float* sas = (float*)(smem + SM_ATT);
    float* sad = (float*)(smem + SM_ATT + 1024);

    int tid = threadIdx.x;
    int wid = tid >> 5, lane = tid & 31;
    int row0 = blockIdx.y * 128, col0 = blockIdx.x * 128;

    for (int i = tid; i < 256; i += 256) {
        sas[i] = att_s[i];
        sad[i] = att_d[i];
    }

    for (int i = tid; i < 128 * 16; i += 256) {
        int r = i >> 4, c8 = (i & 15) * 8;
        int gr = row0 + r;
        uint4 pk = make_uint4(0u, 0u, 0u, 0u);
        if (gr < M) pk = *(const uint4*)&g_xh[(size_t)gr * 128 + c8];
        *(uint4*)&As[r * LDA + c8] = pk;
    }
    for (int i = tid; i < 128 * 16; i += 256) {
        int n = i >> 4, c8 = (i & 15) * 8;
        uint4 pk = *(const uint4*)&g_w1t[(size_t)(col0 + n) * 128 + c8];
        *(uint4*)&Bs[n * LDA + c8] = pk;
    }
    __syncthreads();

    int wm = wid & 3, wn = wid >> 2;
    int m0w = wm * 32, n0w = wn * 64;

    float acc[2][8][4];
    #pragma unroll
    for (int mi = 0; mi < 2; mi++)
        #pragma unroll
        for (int ni = 0; ni < 8; ni++)
            #pragma unroll
            for (int q = 0; q < 4; q++) acc[mi][ni][q] = 0.f;

    uint32_t aRow = (uint32_t)(m0w + (lane & 7) + ((lane >> 3) & 1) * 8);
    uint32_t aK   = (uint32_t)((lane >> 4) * 8);
    uint32_t aBase = sb + SM_A + (aRow * LDA + aK) * 2;
    uint32_t bRow = (uint32_t)(n0w + (lane >> 4) * 8 + (lane & 7));
    uint32_t bK   = (uint32_t)(((lane >> 3) & 1) * 8);
    uint32_t bBase = sb + SM_B + (bRow * LDA + bK) * 2;

    #pragma unroll
    for (int ks = 0; ks < 8; ks++) {
        uint32_t k0b = ks * 16 * 2;
        uint32_t af[2][4];
        ldsm4(af[0], aBase + k0b);
        ldsm4(af[1], aBase + k0b + 16 * LDA * 2);
        uint32_t bf[8][2];
        #pragma unroll
        for (int np = 0; np < 4; np++) {
            uint32_t r4[4];
            ldsm4(r4, bBase + k0b + np * 16 * LDA * 2);
            bf[2 * np][0] = r4[0]; bf[2 * np][1] = r4[1];
            bf[2 * np + 1][0] = r4[2]; bf[2 * np + 1][1] = r4[3];
        }
        #pragma unroll
        for (int mi = 0; mi < 2; mi++)
            #pragma unroll
            for (int ni = 0; ni < 8; ni++)
                mma16816(acc[mi][ni], af[mi], bf[ni]);
    }
    __syncthreads();

    int g = lane >> 2, tig = lane & 3;
    #pragma unroll
    for (int mi = 0; mi < 2; mi++) {
        #pragma unroll
        for (int ni = 0; ni < 8; ni++) {
            int r = m0w + mi * 16 + g;
            int c = n0w + ni * 8 + tig * 2;
            float2 lo = make_float2(acc[mi][ni][0], acc[mi][ni][1]);
            float2 hi = make_float2(acc[mi][ni][2], acc[mi][ni][3]);
            *(float2*)&Cs[r * LDC + c] = lo;
            *(float2*)&Cs[(r + 8) * LDC + c] = hi;
        }
    }
    __syncthreads();

    int r = tid & 127, half = tid >> 7;
    int grow = row0 + r;
    if (grow < M) {
        int cl0 = half * 64;
        int hb = (col0 >> 5) + half * 2;
        float ps0 = 0.f, pd0 = 0.f, ps1 = 0.f, pd1 = 0.f;
        __half2 hh[32];
        #pragma unroll
        for (int j = 0; j < 16; j++) {
            float4 v = *(const float4*)&Cs[r * LDC + cl0 + j * 4];
            int gc = col0 + cl0 + j * 4;
            if (j < 8) {
                ps0 = fmaf(v.x, sas[gc], fmaf(v.y, sas[gc + 1],
                      fmaf(v.z, sas[gc + 2], fmaf(v.w, sas[gc + 3], ps0))));
                pd0 = fmaf(v.x, sad[gc], fmaf(v.y, sad[gc + 1],
                      fmaf(v.z, sad[gc + 2], fmaf(v.w, sad[gc + 3], pd0))));
            } else {
                ps1 = fmaf(v.x, sas[gc], fmaf(v.y, sas[gc + 1],
                      fmaf(v.z, sas[gc + 2], fmaf(v.w, sas[gc + 3], ps1))));
                pd1 = fmaf(v.x, sad[gc], fmaf(v.y, sad[gc + 1],
                      fmaf(v.z, sad[gc + 2], fmaf(v.w, sad[gc + 3], pd1))));
            }
            hh[j * 2] = __floats2half2_rn(v.x, v.y);
            hh[j * 2 + 1] = __floats2half2_rn(v.z, v.w);
        }
        g_asrc1[grow * 8 + hb] = ps0;
        g_adst1[grow * 8 + hb] = pd0;
        g_asrc1[grow * 8 + hb + 1] = ps1;
        g_adst1[grow * 8 + hb + 1] = pd1;
        uint4* dst = (uint4*)&g_h1h[(size_t)grow * 256 + col0 + cl0];
        #pragma unroll
        for (int q = 0; q < 8; q++) {
            uint4 pk;
            pk.x = *(unsigned*)&hh[q * 4 + 0];
            pk.y = *(unsigned*)&hh[q * 4 + 1];
            pk.z = *(unsigned*)&hh[q * 4 + 2];
            pk.w = *(unsigned*)&hh[q * 4 + 3];
            dst[q] = pk;
        }
    }
}

// ---------------- CSR build -------------------------------------------------
__global__ void k_hist(const void* __restrict__ ei, int E, int N) {
    int i = blockIdx.x * blockDim.x + threadIdx.x;
    if (i >= E + N) return;
    int d;
    if (i < E) {
        d = g_is64 ? (int)((const long long*)ei)[E + i]
                   : ((const int*)ei)[E + i];
    } else {
        d = i - E;
    }
    atomicAdd(&g_cnt[d], 1);
}

__global__ __launch_bounds__(256) void k_scan1(int N) {
    __shared__ int sd[256];
    int i = blockIdx.x * 256 + threadIdx.x;
    int v = (i < N) ? g_cnt[i] : 0;
    sd[threadIdx.x] = v;
    __syncthreads();
    #pragma unroll
    for (int s = 1; s < 256; s <<= 1) {
        int t = (threadIdx.x >= s) ? sd[threadIdx.x - s] : 0;
        __syncthreads();
        sd[threadIdx.x] += t;
        __syncthreads();
    }
    if (i < N) g_off[i] = sd[threadIdx.x] - v;
    if (threadIdx.x == 255) g_bsum[blockIdx.x] = sd[255];
}

__global__ __launch_bounds__(256) void k_scan2(int nb) {
    __shared__ int sd[256];
    int v = (threadIdx.x < nb) ? g_bsum[threadIdx.x] : 0;
    sd[threadIdx.x] = v;
    __syncthreads();
    #pragma unroll
    for (int s = 1; s < 256; s <<= 1) {
        int t = (threadIdx.x >= s) ? sd[threadIdx.x - s] : 0;
        __syncthreads();
        sd[threadIdx.x] += t;
        __syncthreads();
    }
    if (threadIdx.x < nb) g_bsum[threadIdx.x] = sd[threadIdx.x] - v;
}

__global__ __launch_bounds__(256) void k_scan3(int N, int total) {
    int i = blockIdx.x * 256 + threadIdx.x;
    if (i < N) {
        int o = g_off[i] + g_bsum[blockIdx.x];
        g_off[i] = o;
        g_cur[i] = o;
    }
    if (i == 0) g_off[N] = total;
}

__global__ void k_scatter(const void* __restrict__ ei, int E, int N) {
    int i = blockIdx.x * blockDim.x + threadIdx.x;
    if (i >= E + N) return;
    int s, d;
    if (i < E) {
        if (g_is64) {
            const long long* p = (const long long*)ei;
            s = (int)p[i]; d = (int)p[E + i];
        } else {
            const int* p = (const int*)ei;
            s = p[i]; d = p[E + i];
        }
    } else {
        s = d = i - E;
    }
    int pos = atomicAdd(&g_cur[d], 1);
    g_csr[pos] = s;
}

// ------- layer-1: single-pass softmax agg (shfl-free, 4x unroll) -----------
__device__ __forceinline__ void fma8(float* acc, uint4 pk, float w) {
    __half2 h0 = *(__half2*)&pk.x, h1 = *(__half2*)&pk.y;
    __half2 h2 = *(__half2*)&pk.z, h3 = *(__half2*)&pk.w;
    float2 f0 = __half22float2(h0), f1 = __half22float2(h1);
    float2 f2 = __half22float2(h2), f3 = __half22float2(h3);
    acc[0] = fmaf(f0.x, w, acc[0]); acc[1] = fmaf(f0.y, w, acc[1]);
    acc[2] = fmaf(f1.x, w, acc[2]); acc[3] = fmaf(f1.y, w, acc[3]);
    acc[4] = fmaf(f2.x, w, acc[4]); acc[5] = fmaf(f2.y, w, acc[5]);
    acc[6] = fmaf(f3.x, w, acc[6]); acc[7] = fmaf(f3.y, w, acc[7]);
}

__global__ __launch_bounds__(256) void k_agg1(const float* __restrict__ bias1,
                                              const float* __restrict__ W2,
                                              const float* __restrict__ as2,
                                              const float* __restrict__ ad2,
                                              int N) {
    __shared__ float w2s[4096];     // W2 [256][16]
    __shared__ float sv[8][256];    // per-warp elu'd feature vector

    for (int i = threadIdx.x; i < 4096; i += 256) w2s[i] = W2[i];
    __syncthreads();

    int d = (blockIdx.x * blockDim.x + threadIdx.x) >> 5;
    int lane = threadIdx.x & 31;
    int wid = threadIdx.x >> 5;
    if (d >= N) return;
    int beg = g_off[d], end = g_off[d + 1];
    int h = lane >> 2;
    float adv = g_adst1[d * 8 + h];

    float acc[8];
    #pragma unroll
    for (int q = 0; q < 8; q++) acc[q] = 0.f;
    float sumw = 0.f;

    const uint4* base = (const uint4*)g_h1h;
    int e = beg;
    for (; e + 3 < end; e += 4) {
        int s0 = g_csr[e], s1 = g_csr[e + 1], s2 = g_csr[e + 2], s3 = g_csr[e + 3];
        float w0 = __expf(lrelu(g_asrc1[s0 * 8 + h] + adv));
        float w1 = __expf(lrelu(g_asrc1[s1 * 8 + h] + adv));
        float w2 = __expf(lrelu(g_asrc1[s2 * 8 + h] + adv));
        float w3 = __expf(lrelu(g_asrc1[s3 * 8 + h] + adv));
        sumw += (w0 + w1) + (w2 + w3);
        uint4 p0 = base[(size_t)s0 * 32 + lane];
        uint4 p1 = base[(size_t)s1 * 32 + lane];
        uint4 p2 = base[(size_t)s2 * 32 + lane];
        uint4 p3 = base[(size_t)s3 * 32 + lane];
        fma8(acc, p0, w0);
        fma8(acc, p1, w1);
        fma8(acc, p2, w2);
        fma8(acc, p3, w3);
    }
    for (; e < end; e++) {
        int s0 = g_csr[e];
        float w0 = __expf(lrelu(g_asrc1[s0 * 8 + h] + adv));
        sumw += w0;
        uint4 p0 = base[(size_t)s0 * 32 + lane];
        fma8(acc, p0, w0);
    }
    float inv = 1.f / (sumw + 1e-16f);

    const float* bp = bias1 + lane * 8;
    float* svp = &sv[wid][lane * 8];
    #pragma unroll
    for (int q = 0; q < 8; q++) {
        float v = fmaf(acc[q], inv, bp[q]);
        svp[q] = v > 0.f ? v : expm1f(v);
    }
    __syncwarp();

    int n = lane & 15, half = lane >> 4;
    float yp = 0.f;
    #pragma unroll 8
    for (int t = 0; t < 128; t++) {
        int c = 2 * t + half;
        yp = fmaf(sv[wid][c], w2s[c * 16 + n], yp);
    }
    yp += __shfl_xor_sync(0xffffffffu, yp, 16);

    float ps = 0.f, pd = 0.f;
    if (lane < 16) {
        g_h2[d * 16 + lane] = yp;
        ps = yp * __ldg(&as2[lane]);
        pd = yp * __ldg(&ad2[lane]);
    }
    ps = warp_sum(ps);
    pd = warp_sum(pd);
    if (lane == 0) { g_asrc2[d] = ps; g_adst2[d] = pd; }
}

// ------- layer-2: single-pass softmax agg (half-warp per dst, 4x unroll) ---
__global__ __launch_bounds__(256) void k_agg2(const float* __restrict__ bias2,
                                              float* __restrict__ out, int N) {
    int lane = threadIdx.x & 31;
    int half = lane >> 4, l16 = lane & 15;
    int d = ((blockIdx.x * blockDim.x + threadIdx.x) >> 5) * 2 + half;
    if (d >= N) return;
    int beg = g_off[d], end = g_off[d + 1];
    float ad = g_adst2[d];

    float acc = 0.f, sumw = 0.f;
    int e = beg;
    for (; e + 3 < end; e += 4) {
        int s0 = g_csr[e], s1 = g_csr[e + 1], s2 = g_csr[e + 2], s3 = g_csr[e + 3];
        float w0 = __expf(lrelu(g_asrc2[s0] + ad));
        float w1 = __expf(lrelu(g_asrc2[s1] + ad));
        float w2 = __expf(lrelu(g_asrc2[s2] + ad));
        float w3 = __expf(lrelu(g_asrc2[s3] + ad));
        sumw += (w0 + w1) + (w2 + w3);
        acc = fmaf(g_h2[s0 * 16 + l16], w0,
              fmaf(g_h2[s1 * 16 + l16], w1,
              fmaf(g_h2[s2 * 16 + l16], w2,
              fmaf(g_h2[s3 * 16 + l16], w3, acc))));
    }
    for (; e < end; e++) {
        int s0 = g_csr[e];
        float w0 = __expf(lrelu(g_asrc2[s0] + ad));
        sumw += w0;
        acc = fmaf(g_h2[s0 * 16 + l16], w0, acc);
    }
    float inv = 1.f / (sumw + 1e-16f);
    out[d * 16 + l16] = fmaf(acc, inv, bias2[l16]);
}

// ---------------- launch ----------------------------------------------------
extern "C" void kernel_launch(void* const* d_in, const int* in_sizes, int n_in,
                              void* d_out, int out_size) {
    const float* x   = (const float*)d_in[0];
    const void*  ei  = d_in[1];
    const float* W1  = (const float*)d_in[2];
    const float* as1 = (const float*)d_in[3];
    const float* ad1 = (const float*)d_in[4];
    const float* b1  = (const float*)d_in[5];
    const float* W2  = (const float*)d_in[6];
    const float* as2 = (const float*)d_in[7];
    const float* ad2 = (const float*)d_in[8];
    const float* b2  = (const float*)d_in[9];
    float* out = (float*)d_out;

    int N = in_sizes[0] / 128;
    int E = in_sizes[1] / 2;
    int tot = E + N;
    int nb = (N + 255) / 256;

    static cudaStream_t s2 = nullptr;
    static cudaEvent_t evA = nullptr, evB = nullptr;
    if (!s2) {
        cudaStreamCreateWithFlags(&s2, cudaStreamNonBlocking);
        cudaEventCreateWithFlags(&evA, cudaEventDisableTiming);
        cudaEventCreateWithFlags(&evB, cudaEventDisableTiming);
        cudaFuncSetAttribute(k_gemm1, cudaFuncAttributeMaxDynamicSharedMemorySize, SM_TOT);
    }

    // fork immediately: gemm leg (initx+gemm1) on s2, CSR leg on stream 0
    cudaEventRecord(evA, 0);
    cudaStreamWaitEvent(s2, evA, 0);

    k_initx<<<196, 256, 0, s2>>>(N, W1, x);
    dim3 g1(2, (N + 127) / 128);
    k_gemm1<<<g1, 256, SM_TOT, s2>>>(as1, ad1, N);
    cudaEventRecord(evB, s2);

    k_init0<<<(N + 511) / 512, 512>>>((const int*)ei, in_sizes[1], N);
    k_hist<<<(tot + 255) / 256, 256>>>(ei, E, N);
    k_scan1<<<nb, 256>>>(N);
    k_scan2<<<1, 256>>>(nb);
    k_scan3<<<nb, 256>>>(N, tot);
    k_scatter<<<(tot + 255) / 256, 256>>>(ei, E, N);

    cudaStreamWaitEvent(0, evB, 0);

    k_agg1<<<(N * 32 + 255) / 256, 256>>>(b1, W2, as2, ad2, N);
    k_agg2<<<(N * 16 + 255) / 256, 256>>>(b2, out, N);
}